// round 1
// baseline (speedup 1.0000x reference)
#include <cuda_runtime.h>
#include <cuda_bf16.h>
#include <math.h>

#define DIM 4096
#define NH  32
#define NKV 8
#define HD  128
#define B_  2
#define S_  2048
#define T_  (B_*S_)          // 4096 tokens
#define NREP 4

// ---------------- scratch (device globals; no cudaMalloc allowed) ----------
__device__ float g_q[(size_t)T_ * NH  * HD];   // (T, 4096)  64 MB
__device__ float g_k[(size_t)T_ * NKV * HD];   // (T, 1024)  16 MB
__device__ float g_v[(size_t)T_ * NKV * HD];   // (T, 1024)  16 MB
__device__ float g_o[(size_t)T_ * NH  * HD];   // (T, 4096)  64 MB

// ---------------- generic fp32 SGEMM: C[M,N] = A[M,K] * W[K,N] -------------
// BM=128, BN=128, BK=16, 256 threads, 8x8 per-thread tile.
// Requires M%128==0, N%128==0, K%16==0 (true for all our shapes).
__global__ __launch_bounds__(256) void sgemm_kernel(
    const float* __restrict__ A, const float* __restrict__ W,
    float* __restrict__ C, int M, int N, int K)
{
    __shared__ float As[16][128];   // transposed A tile: As[k][m]
    __shared__ float Bs[16][128];

    const int tid  = threadIdx.x;
    const int m0   = blockIdx.y * 128;
    const int n0   = blockIdx.x * 128;
    const int trow = (tid >> 4) * 8;   // 0..120
    const int tcol = (tid & 15) * 8;   // 0..120

    float acc[8][8];
    #pragma unroll
    for (int i = 0; i < 8; i++)
        #pragma unroll
        for (int j = 0; j < 8; j++) acc[i][j] = 0.f;

    for (int k0 = 0; k0 < K; k0 += 16) {
        // A tile: 128 rows x 16 cols = 512 float4
        #pragma unroll
        for (int i = 0; i < 2; i++) {
            int id = tid + i * 256;
            int r  = id >> 2;
            int c4 = id & 3;
            float4 v = *(const float4*)(A + (size_t)(m0 + r) * K + k0 + c4 * 4);
            As[c4*4+0][r] = v.x;
            As[c4*4+1][r] = v.y;
            As[c4*4+2][r] = v.z;
            As[c4*4+3][r] = v.w;
        }
        // W tile: 16 rows x 128 cols = 512 float4
        #pragma unroll
        for (int i = 0; i < 2; i++) {
            int id = tid + i * 256;
            int r  = id >> 5;
            int c4 = id & 31;
            *(float4*)&Bs[r][c4*4] =
                *(const float4*)(W + (size_t)(k0 + r) * N + n0 + c4 * 4);
        }
        __syncthreads();

        #pragma unroll
        for (int kk = 0; kk < 16; kk++) {
            float a[8], b[8];
            *(float4*)&a[0] = *(float4*)&As[kk][trow];
            *(float4*)&a[4] = *(float4*)&As[kk][trow + 4];
            *(float4*)&b[0] = *(float4*)&Bs[kk][tcol];
            *(float4*)&b[4] = *(float4*)&Bs[kk][tcol + 4];
            #pragma unroll
            for (int i = 0; i < 8; i++)
                #pragma unroll
                for (int j = 0; j < 8; j++)
                    acc[i][j] += a[i] * b[j];
        }
        __syncthreads();
    }

    #pragma unroll
    for (int i = 0; i < 8; i++) {
        float* cp = C + (size_t)(m0 + trow + i) * N + n0 + tcol;
        *(float4*)(cp)     = make_float4(acc[i][0], acc[i][1], acc[i][2], acc[i][3]);
        *(float4*)(cp + 4) = make_float4(acc[i][4], acc[i][5], acc[i][6], acc[i][7]);
    }
}

// ---------------- RoPE over Q (NH heads) and K (NKV heads) -----------------
__global__ void rope_kernel(const float* __restrict__ fcos,
                            const float* __restrict__ fsin)
{
    int idx = blockIdx.x * blockDim.x + threadIdx.x;
    const int total = T_ * (NH + NKV) * (HD / 2);
    if (idx >= total) return;
    int d    = idx % (HD / 2);
    int rest = idx / (HD / 2);
    int h    = rest % (NH + NKV);
    int t    = rest / (NH + NKV);
    int s    = t % S_;                     // start_pos == 0
    float c  = fcos[s * (HD / 2) + d];
    float sn = fsin[s * (HD / 2) + d];
    float* p;
    if (h < NH) p = g_q + ((size_t)t * NH  + h)        * HD + 2 * d;
    else        p = g_k + ((size_t)t * NKV + (h - NH)) * HD + 2 * d;
    float x0 = p[0], x1 = p[1];
    p[0] = x0 * c - x1 * sn;
    p[1] = x0 * sn + x1 * c;
}

// ---------------- flash attention (fp32, causal, GQA) ----------------------
// Block = 64 q-rows x (loop over 64-kv tiles) for one (batch, head).
// 256 threads: rowg = tid>>4 (16 groups of 4 rows), colg = tid&15.
// Score sub-tile per thread: 4x4. O sub-tile per thread: 4 rows x 8 cols.
#define Q_STRIDE 132
#define K_STRIDE 129
#define V_STRIDE 128
#define P_STRIDE 68
#define ATTN_SMEM ((64*Q_STRIDE + 64*K_STRIDE + 64*V_STRIDE + 64*P_STRIDE) * 4)

__global__ __launch_bounds__(256, 1) void attn_kernel()
{
    extern __shared__ float sm[];
    float* Qs = sm;                       // [64][132]
    float* Ks = Qs + 64 * Q_STRIDE;       // [64][129]
    float* Vs = Ks + 64 * K_STRIDE;       // [64][128]
    float* Pt = Vs + 64 * V_STRIDE;       // [64][68]   Pt[k][r]

    const int tid  = threadIdx.x;
    const int rowg = tid >> 4;
    const int colg = tid & 15;
    const int qm0  = blockIdx.x * 64;
    const int h    = blockIdx.y;
    const int bb   = blockIdx.z;
    const int g    = h >> 2;              // kv group (NREP = 4)

    const float* Qg = g_q + ((size_t)(bb * S_ + qm0) * NH + h) * HD;
    const float* Kg = g_k + ((size_t)(bb * S_) * NKV + g) * HD;
    const float* Vg = g_v + ((size_t)(bb * S_) * NKV + g) * HD;

    // load Q tile (64 x 128)
    #pragma unroll
    for (int i = 0; i < 8; i++) {
        int id = tid + i * 256;
        int r  = id >> 5, c4 = id & 31;
        float4 vq = *(const float4*)(Qg + (size_t)r * (NH * HD) + c4 * 4);
        *(float4*)(Qs + r * Q_STRIDE + c4 * 4) = vq;
    }

    float o[4][8];
    #pragma unroll
    for (int i = 0; i < 4; i++)
        #pragma unroll
        for (int j = 0; j < 8; j++) o[i][j] = 0.f;
    float mrow[4] = {-1e30f, -1e30f, -1e30f, -1e30f};
    float lrow[4] = {0.f, 0.f, 0.f, 0.f};

    const int r0  = rowg * 4;
    const int sc0 = colg * 4;
    const int oc0 = colg * 8;
    const float scale = 0.08838834764831843f;   // 1/sqrt(128)

    const int ntiles = (qm0 >> 6) + 1;
    for (int t = 0; t < ntiles; t++) {
        const int j0 = t * 64;
        __syncthreads();   // K/V/Pt reuse fence from previous iteration
        // load K,V tiles (64 x 128 each)
        #pragma unroll
        for (int i = 0; i < 8; i++) {
            int id = tid + i * 256;
            int r  = id >> 5, c4 = id & 31;
            float4 k4 = *(const float4*)(Kg + (size_t)(j0 + r) * (NKV * HD) + c4 * 4);
            float* kd = Ks + r * K_STRIDE + c4 * 4;
            kd[0] = k4.x; kd[1] = k4.y; kd[2] = k4.z; kd[3] = k4.w;
            float4 v4 = *(const float4*)(Vg + (size_t)(j0 + r) * (NKV * HD) + c4 * 4);
            *(float4*)(Vs + r * V_STRIDE + c4 * 4) = v4;
        }
        __syncthreads();

        // S = Q K^T
        float sacc[4][4];
        #pragma unroll
        for (int i = 0; i < 4; i++)
            #pragma unroll
            for (int j = 0; j < 4; j++) sacc[i][j] = 0.f;
        #pragma unroll 8
        for (int kk = 0; kk < 128; kk++) {
            float aq[4], bk[4];
            #pragma unroll
            for (int i = 0; i < 4; i++) aq[i] = Qs[(r0 + i) * Q_STRIDE + kk];
            #pragma unroll
            for (int j = 0; j < 4; j++) bk[j] = Ks[(sc0 + j) * K_STRIDE + kk];
            #pragma unroll
            for (int i = 0; i < 4; i++)
                #pragma unroll
                for (int j = 0; j < 4; j++)
                    sacc[i][j] += aq[i] * bk[j];
        }

        // scale + causal mask
        #pragma unroll
        for (int i = 0; i < 4; i++) {
            int qrow = qm0 + r0 + i;
            #pragma unroll
            for (int j = 0; j < 4; j++) {
                int kcol = j0 + sc0 + j;
                sacc[i][j] = (kcol <= qrow) ? sacc[i][j] * scale : -1e30f;
            }
        }

        // online softmax stats (reduce over the 16 colg lanes; lane bits 0..3)
        float ptile[4][4];
        #pragma unroll
        for (int i = 0; i < 4; i++) {
            float m = fmaxf(fmaxf(sacc[i][0], sacc[i][1]),
                            fmaxf(sacc[i][2], sacc[i][3]));
            #pragma unroll
            for (int off = 1; off < 16; off <<= 1)
                m = fmaxf(m, __shfl_xor_sync(0xffffffffu, m, off));
            float mnew = fmaxf(mrow[i], m);
            float l = 0.f;
            #pragma unroll
            for (int j = 0; j < 4; j++) {
                float p = __expf(sacc[i][j] - mnew);
                ptile[i][j] = p;
                l += p;
            }
            #pragma unroll
            for (int off = 1; off < 16; off <<= 1)
                l += __shfl_xor_sync(0xffffffffu, l, off);
            float alpha = __expf(mrow[i] - mnew);
            lrow[i] = lrow[i] * alpha + l;
            mrow[i] = mnew;
            #pragma unroll
            for (int jj = 0; jj < 8; jj++) o[i][jj] *= alpha;
        }

        // stage P transposed: Pt[k][r]
        #pragma unroll
        for (int i = 0; i < 4; i++)
            #pragma unroll
            for (int j = 0; j < 4; j++)
                Pt[(sc0 + j) * P_STRIDE + (r0 + i)] = ptile[i][j];
        __syncthreads();

        // O += P V
        #pragma unroll 4
        for (int k = 0; k < 64; k++) {
            float a4[4];
            *(float4*)a4 = *(float4*)(Pt + k * P_STRIDE + r0);
            float b8[8];
            *(float4*)&b8[0] = *(float4*)(Vs + k * V_STRIDE + oc0);
            *(float4*)&b8[4] = *(float4*)(Vs + k * V_STRIDE + oc0 + 4);
            #pragma unroll
            for (int i = 0; i < 4; i++)
                #pragma unroll
                for (int jj = 0; jj < 8; jj++)
                    o[i][jj] += a4[i] * b8[jj];
        }
    }

    // normalize + store
    float* Og = g_o + ((size_t)(bb * S_ + qm0) * NH + h) * HD;
    #pragma unroll
    for (int i = 0; i < 4; i++) {
        float inv = 1.0f / lrow[i];
        float4 w0 = make_float4(o[i][0]*inv, o[i][1]*inv, o[i][2]*inv, o[i][3]*inv);
        float4 w1 = make_float4(o[i][4]*inv, o[i][5]*inv, o[i][6]*inv, o[i][7]*inv);
        *(float4*)(Og + (size_t)(r0 + i) * (NH * HD) + oc0)     = w0;
        *(float4*)(Og + (size_t)(r0 + i) * (NH * HD) + oc0 + 4) = w1;
    }
}

// ---------------- launch ----------------------------------------------------
extern "C" void kernel_launch(void* const* d_in, const int* in_sizes, int n_in,
                              void* d_out, int out_size)
{
    const float* x    = (const float*)d_in[0];
    // d_in[1] = start_pos (int32, always 0 here)
    const float* fcos = (const float*)d_in[2];
    const float* fsin = (const float*)d_in[3];
    // d_in[4] = cache (unused: output doesn't include it)
    // d_in[5] = mask  (unused: causal mask is analytic, start_pos = 0)
    const float* wq   = (const float*)d_in[6];
    const float* wk   = (const float*)d_in[7];
    const float* wv   = (const float*)d_in[8];
    const float* wo   = (const float*)d_in[9];
    float* out        = (float*)d_out;

    float *q, *k, *v, *o;
    cudaGetSymbolAddress((void**)&q, g_q);
    cudaGetSymbolAddress((void**)&k, g_k);
    cudaGetSymbolAddress((void**)&v, g_v);
    cudaGetSymbolAddress((void**)&o, g_o);

    // 1) projections
    sgemm_kernel<<<dim3(DIM / 128, T_ / 128), 256>>>(x, wq, q, T_, NH  * HD, DIM);
    sgemm_kernel<<<dim3((NKV * HD) / 128, T_ / 128), 256>>>(x, wk, k, T_, NKV * HD, DIM);
    sgemm_kernel<<<dim3((NKV * HD) / 128, T_ / 128), 256>>>(x, wv, v, T_, NKV * HD, DIM);

    // 2) RoPE on Q and K
    {
        int total = T_ * (NH + NKV) * (HD / 2);
        rope_kernel<<<(total + 255) / 256, 256>>>(fcos, fsin);
    }

    // 3) attention
    cudaFuncSetAttribute(attn_kernel,
                         cudaFuncAttributeMaxDynamicSharedMemorySize, ATTN_SMEM);
    attn_kernel<<<dim3(S_ / 64, NH, B_), 256, ATTN_SMEM>>>();

    // 4) output projection -> d_out
    sgemm_kernel<<<dim3(DIM / 128, T_ / 128), 256>>>(o, wo, out, T_, DIM, DIM);
}

// round 3
// speedup vs baseline: 1.5196x; 1.5196x over previous
#include <cuda_runtime.h>
#include <cuda_bf16.h>
#include <cstdint>
#include <math.h>

#define DIM 4096
#define NH  32
#define NKV 8
#define HD  128
#define B_  2
#define S_  2048
#define T_  (B_*S_)          // 4096 tokens
#define NREP 4

// ---------------- scratch (device globals; no cudaMalloc allowed) ----------
__device__ float g_q[(size_t)T_ * NH  * HD];
__device__ float g_k[(size_t)T_ * NKV * HD];
__device__ float g_v[(size_t)T_ * NKV * HD];
__device__ float g_o[(size_t)T_ * NH  * HD];

// split-bf16 operands
__device__ __nv_bfloat16 g_xh[(size_t)T_ * DIM];
__device__ __nv_bfloat16 g_xl[(size_t)T_ * DIM];
__device__ __nv_bfloat16 g_oh[(size_t)T_ * DIM];
__device__ __nv_bfloat16 g_ol[(size_t)T_ * DIM];
__device__ __nv_bfloat16 g_wqt_h[(size_t)DIM * DIM];
__device__ __nv_bfloat16 g_wqt_l[(size_t)DIM * DIM];
__device__ __nv_bfloat16 g_wkt_h[(size_t)(NKV*HD) * DIM];
__device__ __nv_bfloat16 g_wkt_l[(size_t)(NKV*HD) * DIM];
__device__ __nv_bfloat16 g_wvt_h[(size_t)(NKV*HD) * DIM];
__device__ __nv_bfloat16 g_wvt_l[(size_t)(NKV*HD) * DIM];
__device__ __nv_bfloat16 g_wot_h[(size_t)DIM * DIM];
__device__ __nv_bfloat16 g_wot_l[(size_t)DIM * DIM];

// ---------------- low-level helpers (sm_103 base-target safe) --------------
__device__ __forceinline__ uint32_t smem_u32(const void* p) {
    uint32_t a;
    asm("{ .reg .u64 t; cvta.to.shared.u64 t, %1; cvt.u32.u64 %0, t; }"
        : "=r"(a) : "l"(p));
    return a;
}
__device__ __forceinline__ void cp_async16(uint32_t dst, const void* src) {
    asm volatile("cp.async.cg.shared.global [%0], [%1], 16;"
                 :: "r"(dst), "l"(src));
}
#define CP_COMMIT() asm volatile("cp.async.commit_group;" ::: "memory")
#define CP_WAIT(n)  asm volatile("cp.async.wait_group %0;" :: "n"(n) : "memory")

__device__ __forceinline__ void ldsm4(uint32_t& r0, uint32_t& r1,
                                      uint32_t& r2, uint32_t& r3, uint32_t a) {
    asm volatile("ldmatrix.sync.aligned.m8n8.x4.shared.b16 {%0,%1,%2,%3}, [%4];"
                 : "=r"(r0), "=r"(r1), "=r"(r2), "=r"(r3) : "r"(a));
}
__device__ __forceinline__ void mma_bf16(float* c, const uint32_t* a,
                                         const uint32_t* b) {
    asm volatile(
        "mma.sync.aligned.m16n8k16.row.col.f32.bf16.bf16.f32 "
        "{%0,%1,%2,%3}, {%4,%5,%6,%7}, {%8,%9}, {%0,%1,%2,%3};"
        : "+f"(c[0]), "+f"(c[1]), "+f"(c[2]), "+f"(c[3])
        : "r"(a[0]), "r"(a[1]), "r"(a[2]), "r"(a[3]), "r"(b[0]), "r"(b[1]));
}

// ---------------- split-bf16 conversion kernels -----------------------------
__device__ __forceinline__ void split_bf16(float x, __nv_bfloat16& h, __nv_bfloat16& l)
{
    h = __float2bfloat16(x);
    l = __float2bfloat16(x - __bfloat162float(h));
}

__global__ void conv_split_kernel(const float* __restrict__ X,
                                  __nv_bfloat16* __restrict__ H,
                                  __nv_bfloat16* __restrict__ L, int n4)
{
    int i = blockIdx.x * blockDim.x + threadIdx.x;
    if (i >= n4) return;
    float4 v = *(const float4*)(X + (size_t)i * 4);
    __nv_bfloat16 h[4], l[4];
    split_bf16(v.x, h[0], l[0]);
    split_bf16(v.y, h[1], l[1]);
    split_bf16(v.z, h[2], l[2]);
    split_bf16(v.w, h[3], l[3]);
    *(uint2*)(H + (size_t)i * 4) = *(uint2*)h;
    *(uint2*)(L + (size_t)i * 4) = *(uint2*)l;
}

// transpose + split: W[K=DIM, N] -> T[N, DIM] (hi/lo)
__global__ void wconv_kernel(const float* __restrict__ W,
                             __nv_bfloat16* __restrict__ H,
                             __nv_bfloat16* __restrict__ L, int N)
{
    __shared__ float t[32][33];
    const int n0 = blockIdx.x * 32;
    const int k0 = blockIdx.y * 32;
    const int tx = threadIdx.x;
    const int ty = threadIdx.y;
    #pragma unroll
    for (int i = 0; i < 4; i++)
        t[ty + 8 * i][tx] = W[(size_t)(k0 + ty + 8 * i) * N + n0 + tx];
    __syncthreads();
    #pragma unroll
    for (int i = 0; i < 4; i++) {
        float v = t[tx][ty + 8 * i];
        __nv_bfloat16 h, l;
        split_bf16(v, h, l);
        size_t o = (size_t)(n0 + ty + 8 * i) * DIM + k0 + tx;
        H[o] = h;
        L[o] = l;
    }
}

// ---------------- HMMA split-bf16 GEMM --------------------------------------
// C[M,N] = A[M,K=4096] * B^T, B rows are [N,K]. 3 passes: AhBh + AhBl + AlBh.
// Block tile 128x128, BK=32, 256 thr (8 warps, 2x4), cp.async 3-stage pipe.
#define GK       DIM
#define GCHUNKS  (GK / 32)          // 128
#define OPB      8192               // bytes per operand buffer (128 rows x 4 chunks x 16B)
#define STAGEB   (4 * OPB)          // 32 KB per stage
#define NSTAGE   3
#define GEMM_SMEM (NSTAGE * STAGEB) // 96 KB

// smem chunk address: operand-local, 16B chunks; kg = 16B-group in k (0..3)
__device__ __forceinline__ uint32_t chunk_off(int row, int kg) {
    return (uint32_t)(kg * 128 + ((row + 2 * kg) & 127)) * 16u;
}

__global__ __launch_bounds__(256, 1) void gemm_hmma(
    const __nv_bfloat16* __restrict__ Ah, const __nv_bfloat16* __restrict__ Al,
    const __nv_bfloat16* __restrict__ Bh, const __nv_bfloat16* __restrict__ Bl,
    float* __restrict__ C, int N)
{
    extern __shared__ char smg[];
    const uint32_t sbase = smem_u32(smg);

    const int tid = threadIdx.x;
    const int wid = tid >> 5;
    const int lid = tid & 31;
    const int wm  = wid >> 2;      // 0..1
    const int wn  = wid & 3;       // 0..3
    const int m0  = blockIdx.y * 128;
    const int n0  = blockIdx.x * 128;

    // ---- loader mapping: t -> (kg, row), 2 rows per operand per thread ----
    const int lkg = tid & 3;
    const int lr  = tid >> 2;      // 0..63

    auto load_stage = [&](int stage, int kc) {
        const uint32_t sb = sbase + stage * STAGEB;
        const size_t koff = (size_t)kc * 32 + lkg * 8;
        #pragma unroll
        for (int i = 0; i < 2; i++) {
            const int r = lr + i * 64;
            const uint32_t co = chunk_off(r, lkg);
            const size_t ga = (size_t)(m0 + r) * GK + koff;
            const size_t gb = (size_t)(n0 + r) * GK + koff;
            cp_async16(sb + 0 * OPB + co, Ah + ga);
            cp_async16(sb + 1 * OPB + co, Al + ga);
            cp_async16(sb + 2 * OPB + co, Bh + gb);
            cp_async16(sb + 3 * OPB + co, Bl + gb);
        }
    };

    // ---- accumulators: 4 m-tiles x 4 n-tiles x 4 floats --------------------
    float acc[4][4][4];
    #pragma unroll
    for (int i = 0; i < 4; i++)
        #pragma unroll
        for (int j = 0; j < 4; j++)
            #pragma unroll
            for (int k = 0; k < 4; k++) acc[i][j][k] = 0.f;

    // ldmatrix lane geometry
    const int sel  = lid >> 3;     // 0..3 (matrix index)
    const int lsub = lid & 7;
    // A lanes: matrices [m0k0, m8k0, m0k8, m8k8]
    const int a_mo = lsub + ((sel & 1) << 3);
    const int a_kg = sel >> 1;
    // B lanes: matrices [n0k0, n0k8, n8k0, n8k8]
    const int b_no = lsub + ((sel >> 1) << 3);
    const int b_kg = sel & 1;

    // prologue: stages 0,1
    load_stage(0, 0); CP_COMMIT();
    load_stage(1, 1); CP_COMMIT();

    for (int kc = 0; kc < GCHUNKS; kc++) {
        const int s = kc % NSTAGE;
        CP_WAIT(1);
        __syncthreads();

        if (kc + 2 < GCHUNKS) load_stage((kc + 2) % NSTAGE, kc + 2);
        CP_COMMIT();

        const uint32_t sb = sbase + s * STAGEB;

        #pragma unroll
        for (int ks = 0; ks < 2; ks++) {
            const int kgA = ks * 2 + a_kg;
            const int kgB = ks * 2 + b_kg;

            uint32_t afh[4][4], afl[4][4];
            #pragma unroll
            for (int mt = 0; mt < 4; mt++) {
                const int m = wm * 64 + mt * 16 + a_mo;
                const uint32_t co = chunk_off(m, kgA);
                ldsm4(afh[mt][0], afh[mt][1], afh[mt][2], afh[mt][3],
                      sb + 0 * OPB + co);
                ldsm4(afl[mt][0], afl[mt][1], afl[mt][2], afl[mt][3],
                      sb + 1 * OPB + co);
            }
            uint32_t bf[2][4];
            // pass 1+2: Bh
            #pragma unroll
            for (int nt2 = 0; nt2 < 2; nt2++) {
                const int n = wn * 32 + nt2 * 16 + b_no;
                const uint32_t co = chunk_off(n, kgB);
                ldsm4(bf[nt2][0], bf[nt2][1], bf[nt2][2], bf[nt2][3],
                      sb + 2 * OPB + co);
            }
            #pragma unroll
            for (int mt = 0; mt < 4; mt++)
                #pragma unroll
                for (int nt = 0; nt < 4; nt++) {
                    uint32_t b2[2] = { bf[nt >> 1][(nt & 1) * 1 + 0 + ((nt & 1) << 1)],
                                       bf[nt >> 1][1 + ((nt & 1) << 1)] };
                    // b regs for n-tile: even -> (R0,R1), odd -> (R2,R3)
                    b2[0] = bf[nt >> 1][(nt & 1) << 1];
                    b2[1] = bf[nt >> 1][((nt & 1) << 1) + 1];
                    mma_bf16(acc[mt][nt], afh[mt], b2);
                    mma_bf16(acc[mt][nt], afl[mt], b2);
                }
            // pass 3: Bl (reuse bf regs)
            #pragma unroll
            for (int nt2 = 0; nt2 < 2; nt2++) {
                const int n = wn * 32 + nt2 * 16 + b_no;
                const uint32_t co = chunk_off(n, kgB);
                ldsm4(bf[nt2][0], bf[nt2][1], bf[nt2][2], bf[nt2][3],
                      sb + 3 * OPB + co);
            }
            #pragma unroll
            for (int mt = 0; mt < 4; mt++)
                #pragma unroll
                for (int nt = 0; nt < 4; nt++) {
                    uint32_t b2[2] = { bf[nt >> 1][(nt & 1) << 1],
                                       bf[nt >> 1][((nt & 1) << 1) + 1] };
                    mma_bf16(acc[mt][nt], afh[mt], b2);
                }
        }
    }

    // ---- epilogue: write fp32 C --------------------------------------------
    const int crow = lid >> 2;
    const int ccol = (lid & 3) * 2;
    #pragma unroll
    for (int mt = 0; mt < 4; mt++) {
        const int r0 = m0 + wm * 64 + mt * 16 + crow;
        #pragma unroll
        for (int nt = 0; nt < 4; nt++) {
            const int c0 = n0 + wn * 32 + nt * 8 + ccol;
            *(float2*)(C + (size_t)r0 * N + c0) =
                make_float2(acc[mt][nt][0], acc[mt][nt][1]);
            *(float2*)(C + (size_t)(r0 + 8) * N + c0) =
                make_float2(acc[mt][nt][2], acc[mt][nt][3]);
        }
    }
}

// ---------------- RoPE over Q (NH heads) and K (NKV heads) -----------------
__global__ void rope_kernel(const float* __restrict__ fcos,
                            const float* __restrict__ fsin)
{
    int idx = blockIdx.x * blockDim.x + threadIdx.x;
    const int total = T_ * (NH + NKV) * (HD / 2);
    if (idx >= total) return;
    int d    = idx % (HD / 2);
    int rest = idx / (HD / 2);
    int h    = rest % (NH + NKV);
    int t    = rest / (NH + NKV);
    int s    = t % S_;
    float c  = fcos[s * (HD / 2) + d];
    float sn = fsin[s * (HD / 2) + d];
    float* p;
    if (h < NH) p = g_q + ((size_t)t * NH  + h)        * HD + 2 * d;
    else        p = g_k + ((size_t)t * NKV + (h - NH)) * HD + 2 * d;
    float x0 = p[0], x1 = p[1];
    p[0] = x0 * c - x1 * sn;
    p[1] = x0 * sn + x1 * c;
}

// ---------------- flash attention (fp32, causal, GQA) ----------------------
#define Q_STRIDE 132
#define K_STRIDE 129
#define V_STRIDE 128
#define P_STRIDE 68
#define ATTN_SMEM ((64*Q_STRIDE + 64*K_STRIDE + 64*V_STRIDE + 64*P_STRIDE) * 4)

__global__ __launch_bounds__(256, 1) void attn_kernel()
{
    extern __shared__ float sm[];
    float* Qs = sm;
    float* Ks = Qs + 64 * Q_STRIDE;
    float* Vs = Ks + 64 * K_STRIDE;
    float* Pt = Vs + 64 * V_STRIDE;

    const int tid  = threadIdx.x;
    const int rowg = tid >> 4;
    const int colg = tid & 15;
    const int qm0  = blockIdx.x * 64;
    const int h    = blockIdx.y;
    const int bb   = blockIdx.z;
    const int g    = h >> 2;

    const float* Qg = g_q + ((size_t)(bb * S_ + qm0) * NH + h) * HD;
    const float* Kg = g_k + ((size_t)(bb * S_) * NKV + g) * HD;
    const float* Vg = g_v + ((size_t)(bb * S_) * NKV + g) * HD;

    #pragma unroll
    for (int i = 0; i < 8; i++) {
        int id = tid + i * 256;
        int r  = id >> 5, c4 = id & 31;
        float4 vq = *(const float4*)(Qg + (size_t)r * (NH * HD) + c4 * 4);
        *(float4*)(Qs + r * Q_STRIDE + c4 * 4) = vq;
    }

    float o[4][8];
    #pragma unroll
    for (int i = 0; i < 4; i++)
        #pragma unroll
        for (int j = 0; j < 8; j++) o[i][j] = 0.f;
    float mrow[4] = {-1e30f, -1e30f, -1e30f, -1e30f};
    float lrow[4] = {0.f, 0.f, 0.f, 0.f};

    const int r0  = rowg * 4;
    const int sc0 = colg * 4;
    const int oc0 = colg * 8;
    const float scale = 0.08838834764831843f;

    const int ntiles = (qm0 >> 6) + 1;
    for (int t = 0; t < ntiles; t++) {
        const int j0 = t * 64;
        __syncthreads();
        #pragma unroll
        for (int i = 0; i < 8; i++) {
            int id = tid + i * 256;
            int r  = id >> 5, c4 = id & 31;
            float4 k4 = *(const float4*)(Kg + (size_t)(j0 + r) * (NKV * HD) + c4 * 4);
            float* kd = Ks + r * K_STRIDE + c4 * 4;
            kd[0] = k4.x; kd[1] = k4.y; kd[2] = k4.z; kd[3] = k4.w;
            float4 v4 = *(const float4*)(Vg + (size_t)(j0 + r) * (NKV * HD) + c4 * 4);
            *(float4*)(Vs + r * V_STRIDE + c4 * 4) = v4;
        }
        __syncthreads();

        float sacc[4][4];
        #pragma unroll
        for (int i = 0; i < 4; i++)
            #pragma unroll
            for (int j = 0; j < 4; j++) sacc[i][j] = 0.f;
        #pragma unroll 8
        for (int kk = 0; kk < 128; kk++) {
            float aq[4], bk[4];
            #pragma unroll
            for (int i = 0; i < 4; i++) aq[i] = Qs[(r0 + i) * Q_STRIDE + kk];
            #pragma unroll
            for (int j = 0; j < 4; j++) bk[j] = Ks[(sc0 + j) * K_STRIDE + kk];
            #pragma unroll
            for (int i = 0; i < 4; i++)
                #pragma unroll
                for (int j = 0; j < 4; j++)
                    sacc[i][j] += aq[i] * bk[j];
        }

        #pragma unroll
        for (int i = 0; i < 4; i++) {
            int qrow = qm0 + r0 + i;
            #pragma unroll
            for (int j = 0; j < 4; j++) {
                int kcol = j0 + sc0 + j;
                sacc[i][j] = (kcol <= qrow) ? sacc[i][j] * scale : -1e30f;
            }
        }

        float ptile[4][4];
        #pragma unroll
        for (int i = 0; i < 4; i++) {
            float m = fmaxf(fmaxf(sacc[i][0], sacc[i][1]),
                            fmaxf(sacc[i][2], sacc[i][3]));
            #pragma unroll
            for (int off = 1; off < 16; off <<= 1)
                m = fmaxf(m, __shfl_xor_sync(0xffffffffu, m, off));
            float mnew = fmaxf(mrow[i], m);
            float l = 0.f;
            #pragma unroll
            for (int j = 0; j < 4; j++) {
                float p = __expf(sacc[i][j] - mnew);
                ptile[i][j] = p;
                l += p;
            }
            #pragma unroll
            for (int off = 1; off < 16; off <<= 1)
                l += __shfl_xor_sync(0xffffffffu, l, off);
            float alpha = __expf(mrow[i] - mnew);
            lrow[i] = lrow[i] * alpha + l;
            mrow[i] = mnew;
            #pragma unroll
            for (int jj = 0; jj < 8; jj++) o[i][jj] *= alpha;
        }

        #pragma unroll
        for (int i = 0; i < 4; i++)
            #pragma unroll
            for (int j = 0; j < 4; j++)
                Pt[(sc0 + j) * P_STRIDE + (r0 + i)] = ptile[i][j];
        __syncthreads();

        #pragma unroll 4
        for (int k = 0; k < 64; k++) {
            float a4[4];
            *(float4*)a4 = *(float4*)(Pt + k * P_STRIDE + r0);
            float b8[8];
            *(float4*)&b8[0] = *(float4*)(Vs + k * V_STRIDE + oc0);
            *(float4*)&b8[4] = *(float4*)(Vs + k * V_STRIDE + oc0 + 4);
            #pragma unroll
            for (int i = 0; i < 4; i++)
                #pragma unroll
                for (int jj = 0; jj < 8; jj++)
                    o[i][jj] += a4[i] * b8[jj];
        }
    }

    float* Og = g_o + ((size_t)(bb * S_ + qm0) * NH + h) * HD;
    #pragma unroll
    for (int i = 0; i < 4; i++) {
        float inv = 1.0f / lrow[i];
        float4 w0 = make_float4(o[i][0]*inv, o[i][1]*inv, o[i][2]*inv, o[i][3]*inv);
        float4 w1 = make_float4(o[i][4]*inv, o[i][5]*inv, o[i][6]*inv, o[i][7]*inv);
        *(float4*)(Og + (size_t)(r0 + i) * (NH * HD) + oc0)     = w0;
        *(float4*)(Og + (size_t)(r0 + i) * (NH * HD) + oc0 + 4) = w1;
    }
}

// ---------------- launch ----------------------------------------------------
extern "C" void kernel_launch(void* const* d_in, const int* in_sizes, int n_in,
                              void* d_out, int out_size)
{
    const float* x    = (const float*)d_in[0];
    const float* fcos = (const float*)d_in[2];
    const float* fsin = (const float*)d_in[3];
    const float* wq   = (const float*)d_in[6];
    const float* wk   = (const float*)d_in[7];
    const float* wv   = (const float*)d_in[8];
    const float* wo   = (const float*)d_in[9];
    float* out        = (float*)d_out;

    float *q, *k, *v, *o;
    cudaGetSymbolAddress((void**)&q, g_q);
    cudaGetSymbolAddress((void**)&k, g_k);
    cudaGetSymbolAddress((void**)&v, g_v);
    cudaGetSymbolAddress((void**)&o, g_o);
    __nv_bfloat16 *xh, *xl, *oh, *ol;
    __nv_bfloat16 *wqh, *wql, *wkh, *wkl, *wvh, *wvl, *woh, *wol;
    cudaGetSymbolAddress((void**)&xh, g_xh);
    cudaGetSymbolAddress((void**)&xl, g_xl);
    cudaGetSymbolAddress((void**)&oh, g_oh);
    cudaGetSymbolAddress((void**)&ol, g_ol);
    cudaGetSymbolAddress((void**)&wqh, g_wqt_h);
    cudaGetSymbolAddress((void**)&wql, g_wqt_l);
    cudaGetSymbolAddress((void**)&wkh, g_wkt_h);
    cudaGetSymbolAddress((void**)&wkl, g_wkt_l);
    cudaGetSymbolAddress((void**)&wvh, g_wvt_h);
    cudaGetSymbolAddress((void**)&wvl, g_wvt_l);
    cudaGetSymbolAddress((void**)&woh, g_wot_h);
    cudaGetSymbolAddress((void**)&wol, g_wot_l);

    cudaFuncSetAttribute(gemm_hmma, cudaFuncAttributeMaxDynamicSharedMemorySize, GEMM_SMEM);
    cudaFuncSetAttribute(attn_kernel, cudaFuncAttributeMaxDynamicSharedMemorySize, ATTN_SMEM);

    // 0) operand conversion
    conv_split_kernel<<<(T_ * DIM / 4 + 255) / 256, 256>>>(x, xh, xl, T_ * DIM / 4);
    wconv_kernel<<<dim3(DIM / 32, DIM / 32), dim3(32, 8)>>>(wq, wqh, wql, DIM);
    wconv_kernel<<<dim3((NKV * HD) / 32, DIM / 32), dim3(32, 8)>>>(wk, wkh, wkl, NKV * HD);
    wconv_kernel<<<dim3((NKV * HD) / 32, DIM / 32), dim3(32, 8)>>>(wv, wvh, wvl, NKV * HD);
    wconv_kernel<<<dim3(DIM / 32, DIM / 32), dim3(32, 8)>>>(wo, woh, wol, DIM);

    // 1) projections (HMMA split-bf16)
    gemm_hmma<<<dim3(DIM / 128, T_ / 128), 256, GEMM_SMEM>>>(xh, xl, wqh, wql, q, DIM);
    gemm_hmma<<<dim3((NKV * HD) / 128, T_ / 128), 256, GEMM_SMEM>>>(xh, xl, wkh, wkl, k, NKV * HD);
    gemm_hmma<<<dim3((NKV * HD) / 128, T_ / 128), 256, GEMM_SMEM>>>(xh, xl, wvh, wvl, v, NKV * HD);

    // 2) RoPE
    {
        int total = T_ * (NH + NKV) * (HD / 2);
        rope_kernel<<<(total + 255) / 256, 256>>>(fcos, fsin);
    }

    // 3) attention
    attn_kernel<<<dim3(S_ / 64, NH, B_), 256, ATTN_SMEM>>>();

    // 4) output projection
    conv_split_kernel<<<(T_ * DIM / 4 + 255) / 256, 256>>>(o, oh, ol, T_ * DIM / 4);
    gemm_hmma<<<dim3(DIM / 128, T_ / 128), 256, GEMM_SMEM>>>(oh, ol, woh, wol, out, DIM);
}

// round 4
// speedup vs baseline: 1.9843x; 1.3059x over previous
#include <cuda_runtime.h>
#include <cuda_bf16.h>
#include <cstdint>
#include <math.h>

#define DIM 4096
#define NH  32
#define NKV 8
#define HD  128
#define B_  2
#define S_  2048
#define T_  (B_*S_)          // 4096 tokens
#define NREP 4

// ---------------- scratch (device globals; no cudaMalloc allowed) ----------
__device__ float g_q[(size_t)T_ * NH  * HD];
__device__ float g_k[(size_t)T_ * NKV * HD];
__device__ float g_v[(size_t)T_ * NKV * HD];

// split-bf16 operands
__device__ __nv_bfloat16 g_xh[(size_t)T_ * DIM];
__device__ __nv_bfloat16 g_xl[(size_t)T_ * DIM];
__device__ __nv_bfloat16 g_oh[(size_t)T_ * DIM];
__device__ __nv_bfloat16 g_ol[(size_t)T_ * DIM];
__device__ __nv_bfloat16 g_qh[(size_t)T_ * NH * HD];
__device__ __nv_bfloat16 g_ql[(size_t)T_ * NH * HD];
__device__ __nv_bfloat16 g_kh[(size_t)T_ * NKV * HD];
__device__ __nv_bfloat16 g_kl[(size_t)T_ * NKV * HD];
__device__ __nv_bfloat16 g_vh[(size_t)T_ * NKV * HD];
__device__ __nv_bfloat16 g_vl[(size_t)T_ * NKV * HD];
__device__ __nv_bfloat16 g_wqt_h[(size_t)DIM * DIM];
__device__ __nv_bfloat16 g_wqt_l[(size_t)DIM * DIM];
__device__ __nv_bfloat16 g_wkt_h[(size_t)(NKV*HD) * DIM];
__device__ __nv_bfloat16 g_wkt_l[(size_t)(NKV*HD) * DIM];
__device__ __nv_bfloat16 g_wvt_h[(size_t)(NKV*HD) * DIM];
__device__ __nv_bfloat16 g_wvt_l[(size_t)(NKV*HD) * DIM];
__device__ __nv_bfloat16 g_wot_h[(size_t)DIM * DIM];
__device__ __nv_bfloat16 g_wot_l[(size_t)DIM * DIM];

// ---------------- low-level helpers (sm_103 base-target safe) --------------
__device__ __forceinline__ uint32_t smem_u32(const void* p) {
    uint32_t a;
    asm("{ .reg .u64 t; cvta.to.shared.u64 t, %1; cvt.u32.u64 %0, t; }"
        : "=r"(a) : "l"(p));
    return a;
}
__device__ __forceinline__ void cp_async16(uint32_t dst, const void* src) {
    asm volatile("cp.async.cg.shared.global [%0], [%1], 16;"
                 :: "r"(dst), "l"(src));
}
#define CP_COMMIT() asm volatile("cp.async.commit_group;" ::: "memory")
#define CP_WAIT(n)  asm volatile("cp.async.wait_group %0;" :: "n"(n) : "memory")

__device__ __forceinline__ void ldsm4(uint32_t& r0, uint32_t& r1,
                                      uint32_t& r2, uint32_t& r3, uint32_t a) {
    asm volatile("ldmatrix.sync.aligned.m8n8.x4.shared.b16 {%0,%1,%2,%3}, [%4];"
                 : "=r"(r0), "=r"(r1), "=r"(r2), "=r"(r3) : "r"(a));
}
__device__ __forceinline__ void ldsm4t(uint32_t& r0, uint32_t& r1,
                                       uint32_t& r2, uint32_t& r3, uint32_t a) {
    asm volatile("ldmatrix.sync.aligned.m8n8.x4.trans.shared.b16 {%0,%1,%2,%3}, [%4];"
                 : "=r"(r0), "=r"(r1), "=r"(r2), "=r"(r3) : "r"(a));
}
__device__ __forceinline__ void mma_bf16(float* c, const uint32_t* a,
                                         const uint32_t* b) {
    asm volatile(
        "mma.sync.aligned.m16n8k16.row.col.f32.bf16.bf16.f32 "
        "{%0,%1,%2,%3}, {%4,%5,%6,%7}, {%8,%9}, {%0,%1,%2,%3};"
        : "+f"(c[0]), "+f"(c[1]), "+f"(c[2]), "+f"(c[3])
        : "r"(a[0]), "r"(a[1]), "r"(a[2]), "r"(a[3]), "r"(b[0]), "r"(b[1]));
}

// ---------------- split-bf16 conversion ------------------------------------
__device__ __forceinline__ void split_bf16(float x, __nv_bfloat16& h, __nv_bfloat16& l)
{
    h = __float2bfloat16(x);
    l = __float2bfloat16(x - __bfloat162float(h));
}
__device__ __forceinline__ uint32_t pack_bf16(__nv_bfloat16 lo, __nv_bfloat16 hi)
{
    __nv_bfloat162 v;
    v.x = lo; v.y = hi;
    return *(uint32_t*)&v;
}

__global__ void conv_split_kernel(const float* __restrict__ X,
                                  __nv_bfloat16* __restrict__ H,
                                  __nv_bfloat16* __restrict__ L, int n4)
{
    int i = blockIdx.x * blockDim.x + threadIdx.x;
    if (i >= n4) return;
    float4 v = *(const float4*)(X + (size_t)i * 4);
    __nv_bfloat16 h[4], l[4];
    split_bf16(v.x, h[0], l[0]);
    split_bf16(v.y, h[1], l[1]);
    split_bf16(v.z, h[2], l[2]);
    split_bf16(v.w, h[3], l[3]);
    *(uint2*)(H + (size_t)i * 4) = *(uint2*)h;
    *(uint2*)(L + (size_t)i * 4) = *(uint2*)l;
}

// transpose + split: W[K=DIM, N] -> T[N, DIM] (hi/lo)
__global__ void wconv_kernel(const float* __restrict__ W,
                             __nv_bfloat16* __restrict__ H,
                             __nv_bfloat16* __restrict__ L, int N)
{
    __shared__ float t[32][33];
    const int n0 = blockIdx.x * 32;
    const int k0 = blockIdx.y * 32;
    const int tx = threadIdx.x;
    const int ty = threadIdx.y;
    #pragma unroll
    for (int i = 0; i < 4; i++)
        t[ty + 8 * i][tx] = W[(size_t)(k0 + ty + 8 * i) * N + n0 + tx];
    __syncthreads();
    #pragma unroll
    for (int i = 0; i < 4; i++) {
        float v = t[tx][ty + 8 * i];
        __nv_bfloat16 h, l;
        split_bf16(v, h, l);
        size_t o = (size_t)(n0 + ty + 8 * i) * DIM + k0 + tx;
        H[o] = h;
        L[o] = l;
    }
}

// ---------------- prep: RoPE (q,k) + split q/k/v to bf16 h/l ---------------
__global__ void prep_kernel(const float* __restrict__ fcos,
                            const float* __restrict__ fsin)
{
    int idx = blockIdx.x * blockDim.x + threadIdx.x;
    const int total = T_ * (NH + 2 * NKV) * (HD / 2);
    if (idx >= total) return;
    int d    = idx % (HD / 2);
    int rest = idx / (HD / 2);
    int hh   = rest % (NH + 2 * NKV);
    int t    = rest / (NH + 2 * NKV);
    int s    = t % S_;

    float x0, x1;
    __nv_bfloat16* H;
    __nv_bfloat16* L;
    size_t off;
    if (hh < NH + NKV) {
        const float* src;
        if (hh < NH) {
            off = ((size_t)t * NH + hh) * HD + 2 * d;
            src = g_q + off; H = g_qh; L = g_ql;
        } else {
            off = ((size_t)t * NKV + (hh - NH)) * HD + 2 * d;
            src = g_k + off; H = g_kh; L = g_kl;
        }
        float c  = fcos[s * (HD / 2) + d];
        float sn = fsin[s * (HD / 2) + d];
        float a0 = src[0], a1 = src[1];
        x0 = a0 * c - a1 * sn;
        x1 = a0 * sn + a1 * c;
    } else {
        off = ((size_t)t * NKV + (hh - NH - NKV)) * HD + 2 * d;
        x0 = g_v[off]; x1 = g_v[off + 1];
        H = g_vh; L = g_vl;
    }
    __nv_bfloat16 h0, l0, h1, l1;
    split_bf16(x0, h0, l0);
    split_bf16(x1, h1, l1);
    *(uint32_t*)(H + off) = pack_bf16(h0, h1);
    *(uint32_t*)(L + off) = pack_bf16(l0, l1);
}

// ---------------- HMMA split-bf16 GEMM (unchanged from R2) -----------------
#define GK       DIM
#define GCHUNKS  (GK / 32)
#define OPB      8192
#define STAGEB   (4 * OPB)
#define NSTAGE   3
#define GEMM_SMEM (NSTAGE * STAGEB)

__device__ __forceinline__ uint32_t chunk_off(int row, int kg) {
    return (uint32_t)(kg * 128 + ((row + 2 * kg) & 127)) * 16u;
}

__global__ __launch_bounds__(256, 1) void gemm_hmma(
    const __nv_bfloat16* __restrict__ Ah, const __nv_bfloat16* __restrict__ Al,
    const __nv_bfloat16* __restrict__ Bh, const __nv_bfloat16* __restrict__ Bl,
    float* __restrict__ C, int N)
{
    extern __shared__ char smg[];
    const uint32_t sbase = smem_u32(smg);

    const int tid = threadIdx.x;
    const int wid = tid >> 5;
    const int lid = tid & 31;
    const int wm  = wid >> 2;
    const int wn  = wid & 3;
    const int m0  = blockIdx.y * 128;
    const int n0  = blockIdx.x * 128;

    const int lkg = tid & 3;
    const int lr  = tid >> 2;

    auto load_stage = [&](int stage, int kc) {
        const uint32_t sb = sbase + stage * STAGEB;
        const size_t koff = (size_t)kc * 32 + lkg * 8;
        #pragma unroll
        for (int i = 0; i < 2; i++) {
            const int r = lr + i * 64;
            const uint32_t co = chunk_off(r, lkg);
            const size_t ga = (size_t)(m0 + r) * GK + koff;
            const size_t gb = (size_t)(n0 + r) * GK + koff;
            cp_async16(sb + 0 * OPB + co, Ah + ga);
            cp_async16(sb + 1 * OPB + co, Al + ga);
            cp_async16(sb + 2 * OPB + co, Bh + gb);
            cp_async16(sb + 3 * OPB + co, Bl + gb);
        }
    };

    float acc[4][4][4];
    #pragma unroll
    for (int i = 0; i < 4; i++)
        #pragma unroll
        for (int j = 0; j < 4; j++)
            #pragma unroll
            for (int k = 0; k < 4; k++) acc[i][j][k] = 0.f;

    const int sel  = lid >> 3;
    const int lsub = lid & 7;
    const int a_mo = lsub + ((sel & 1) << 3);
    const int a_kg = sel >> 1;
    const int b_no = lsub + ((sel >> 1) << 3);
    const int b_kg = sel & 1;

    load_stage(0, 0); CP_COMMIT();
    load_stage(1, 1); CP_COMMIT();

    for (int kc = 0; kc < GCHUNKS; kc++) {
        const int s = kc % NSTAGE;
        CP_WAIT(1);
        __syncthreads();

        if (kc + 2 < GCHUNKS) load_stage((kc + 2) % NSTAGE, kc + 2);
        CP_COMMIT();

        const uint32_t sb = sbase + s * STAGEB;

        #pragma unroll
        for (int ks = 0; ks < 2; ks++) {
            const int kgA = ks * 2 + a_kg;
            const int kgB = ks * 2 + b_kg;

            uint32_t afh[4][4], afl[4][4];
            #pragma unroll
            for (int mt = 0; mt < 4; mt++) {
                const int m = wm * 64 + mt * 16 + a_mo;
                const uint32_t co = chunk_off(m, kgA);
                ldsm4(afh[mt][0], afh[mt][1], afh[mt][2], afh[mt][3],
                      sb + 0 * OPB + co);
                ldsm4(afl[mt][0], afl[mt][1], afl[mt][2], afl[mt][3],
                      sb + 1 * OPB + co);
            }
            uint32_t bf[2][4];
            #pragma unroll
            for (int nt2 = 0; nt2 < 2; nt2++) {
                const int n = wn * 32 + nt2 * 16 + b_no;
                const uint32_t co = chunk_off(n, kgB);
                ldsm4(bf[nt2][0], bf[nt2][1], bf[nt2][2], bf[nt2][3],
                      sb + 2 * OPB + co);
            }
            #pragma unroll
            for (int mt = 0; mt < 4; mt++)
                #pragma unroll
                for (int nt = 0; nt < 4; nt++) {
                    uint32_t b2[2] = { bf[nt >> 1][(nt & 1) << 1],
                                       bf[nt >> 1][((nt & 1) << 1) + 1] };
                    mma_bf16(acc[mt][nt], afh[mt], b2);
                    mma_bf16(acc[mt][nt], afl[mt], b2);
                }
            #pragma unroll
            for (int nt2 = 0; nt2 < 2; nt2++) {
                const int n = wn * 32 + nt2 * 16 + b_no;
                const uint32_t co = chunk_off(n, kgB);
                ldsm4(bf[nt2][0], bf[nt2][1], bf[nt2][2], bf[nt2][3],
                      sb + 3 * OPB + co);
            }
            #pragma unroll
            for (int mt = 0; mt < 4; mt++)
                #pragma unroll
                for (int nt = 0; nt < 4; nt++) {
                    uint32_t b2[2] = { bf[nt >> 1][(nt & 1) << 1],
                                       bf[nt >> 1][((nt & 1) << 1) + 1] };
                    mma_bf16(acc[mt][nt], afh[mt], b2);
                }
        }
    }

    const int crow = lid >> 2;
    const int ccol = (lid & 3) * 2;
    #pragma unroll
    for (int mt = 0; mt < 4; mt++) {
        const int r0 = m0 + wm * 64 + mt * 16 + crow;
        #pragma unroll
        for (int nt = 0; nt < 4; nt++) {
            const int c0 = n0 + wn * 32 + nt * 8 + ccol;
            *(float2*)(C + (size_t)r0 * N + c0) =
                make_float2(acc[mt][nt][0], acc[mt][nt][1]);
            *(float2*)(C + (size_t)(r0 + 8) * N + c0) =
                make_float2(acc[mt][nt][2], acc[mt][nt][3]);
        }
    }
}

// ---------------- HMMA split-bf16 flash attention ---------------------------
// CTA: 128 q rows x one (b, head). 8 warps, warp = 16 q rows.
// kv tile 64, double-buffered cp.async. 3-pass split numerics throughout.
#define SQH_OFF 0
#define SQL_OFF 32768
#define STG_OFF 65536
#define STG_SZ  65536
#define KH_OFF  0
#define KL_OFF  16384
#define VH_OFF  32768
#define VL_OFF  49152
#define ATTN_SMEM (STG_OFF + 2 * STG_SZ)   // 192 KB

__device__ __forceinline__ uint32_t offq(int r, int c) {
    return (uint32_t)(c * 128 + ((r + 2 * c) & 127)) * 16u;
}
__device__ __forceinline__ uint32_t offkv(int r, int c) {
    return (uint32_t)(c * 64 + ((r + 2 * c) & 63)) * 16u;
}

__global__ __launch_bounds__(256, 1) void attn_hmma()
{
    extern __shared__ char sma[];
    const uint32_t sb = smem_u32(sma);

    const int tid = threadIdx.x;
    const int wid = tid >> 5;
    const int lid = tid & 31;
    const int bx  = blockIdx.x;           // q block (16)
    const int h   = blockIdx.y;           // head
    const int bz  = blockIdx.z;           // batch
    const int g   = h >> 2;               // kv group
    const int qm0 = bx * 128;
    const int tb  = bz * S_;
    const int ntiles = 2 * (bx + 1);

    const int sel  = lid >> 3;
    const int lsub = lid & 7;
    const int a_r  = wid * 16 + lsub + ((sel & 1) << 3);
    const int a_co = sel >> 1;
    const int b_r  = lsub + ((sel >> 1) << 3);
    const int b_co = sel & 1;
    const int v_r  = lsub + ((sel & 1) << 3);
    const int v_co = sel >> 1;

    // ---- loaders ----
    const int lc = tid & 15;
    const int lr = tid >> 4;

    // Q (once) : 128 rows x 16 chunks x {h,l}
    {
        #pragma unroll
        for (int i = 0; i < 8; i++) {
            const int r = lr + 16 * i;
            const size_t go = ((size_t)(tb + qm0 + r) * NH + h) * HD + lc * 8;
            const uint32_t o = offq(r, lc);
            cp_async16(sb + SQH_OFF + o, g_qh + go);
            cp_async16(sb + SQL_OFF + o, g_ql + go);
        }
    }
    auto load_kv = [&](int stage, int t) {
        const uint32_t st = sb + STG_OFF + stage * STG_SZ;
        const int j0 = t * 64;
        #pragma unroll
        for (int i = 0; i < 4; i++) {
            const int r = lr + 16 * i;
            const size_t go = ((size_t)(tb + j0 + r) * NKV + g) * HD + lc * 8;
            const uint32_t o = offkv(r, lc);
            cp_async16(st + KH_OFF + o, g_kh + go);
            cp_async16(st + KL_OFF + o, g_kl + go);
            cp_async16(st + VH_OFF + o, g_vh + go);
            cp_async16(st + VL_OFF + o, g_vl + go);
        }
    };

    load_kv(0, 0); CP_COMMIT();                // group: Q + tile0
    if (ntiles > 1) { load_kv(1, 1); }
    CP_COMMIT();                               // group: tile1 (may be empty)

    // ---- state ----
    float o[16][4];
    #pragma unroll
    for (int i = 0; i < 16; i++)
        #pragma unroll
        for (int j = 0; j < 4; j++) o[i][j] = 0.f;
    float m_lo = -1e30f, m_hi = -1e30f;
    float l_lo = 0.f, l_hi = 0.f;
    const float scale = 0.08838834764831843f;
    const int row_lo = qm0 + wid * 16 + (lid >> 2);
    const int col_l  = (lid & 3) * 2;

    for (int t = 0; t < ntiles; t++) {
        if (t + 1 < ntiles) { CP_WAIT(1); } else { CP_WAIT(0); }
        __syncthreads();

        const uint32_t stb = sb + STG_OFF + (t & 1) * STG_SZ;
        const bool masked = (t >= 2 * bx);
        const int j0 = t * 64;

        // ---- S = Q K^T (3-pass) ----
        float sacc[8][4];
        #pragma unroll
        for (int i = 0; i < 8; i++)
            #pragma unroll
            for (int j = 0; j < 4; j++) sacc[i][j] = 0.f;

        #pragma unroll
        for (int kt = 0; kt < 8; kt++) {
            uint32_t qh[4], ql[4];
            const uint32_t qo = offq(a_r, 2 * kt + a_co);
            ldsm4(qh[0], qh[1], qh[2], qh[3], sb + SQH_OFF + qo);
            ldsm4(ql[0], ql[1], ql[2], ql[3], sb + SQL_OFF + qo);
            uint32_t kh[4][4], kl[4][4];
            #pragma unroll
            for (int np = 0; np < 4; np++) {
                const uint32_t ko = offkv(np * 16 + b_r, 2 * kt + b_co);
                ldsm4(kh[np][0], kh[np][1], kh[np][2], kh[np][3],
                      stb + KH_OFF + ko);
                ldsm4(kl[np][0], kl[np][1], kl[np][2], kl[np][3],
                      stb + KL_OFF + ko);
            }
            #pragma unroll
            for (int nt = 0; nt < 8; nt++) {
                uint32_t bh[2] = { kh[nt >> 1][(nt & 1) << 1],
                                   kh[nt >> 1][((nt & 1) << 1) + 1] };
                uint32_t bl[2] = { kl[nt >> 1][(nt & 1) << 1],
                                   kl[nt >> 1][((nt & 1) << 1) + 1] };
                mma_bf16(sacc[nt], qh, bh);
                mma_bf16(sacc[nt], ql, bh);
                mma_bf16(sacc[nt], qh, bl);
            }
        }

        // ---- scale + causal mask ----
        if (masked) {
            #pragma unroll
            for (int nt = 0; nt < 8; nt++) {
                const int c0 = j0 + nt * 8 + col_l;
                sacc[nt][0] = (c0     <= row_lo)     ? sacc[nt][0] * scale : -1e30f;
                sacc[nt][1] = (c0 + 1 <= row_lo)     ? sacc[nt][1] * scale : -1e30f;
                sacc[nt][2] = (c0     <= row_lo + 8) ? sacc[nt][2] * scale : -1e30f;
                sacc[nt][3] = (c0 + 1 <= row_lo + 8) ? sacc[nt][3] * scale : -1e30f;
            }
        } else {
            #pragma unroll
            for (int nt = 0; nt < 8; nt++)
                #pragma unroll
                for (int e = 0; e < 4; e++) sacc[nt][e] *= scale;
        }

        // ---- online softmax ----
        float mx_lo = -1e30f, mx_hi = -1e30f;
        #pragma unroll
        for (int nt = 0; nt < 8; nt++) {
            mx_lo = fmaxf(mx_lo, fmaxf(sacc[nt][0], sacc[nt][1]));
            mx_hi = fmaxf(mx_hi, fmaxf(sacc[nt][2], sacc[nt][3]));
        }
        #pragma unroll
        for (int off = 1; off < 4; off <<= 1) {
            mx_lo = fmaxf(mx_lo, __shfl_xor_sync(0xffffffffu, mx_lo, off));
            mx_hi = fmaxf(mx_hi, __shfl_xor_sync(0xffffffffu, mx_hi, off));
        }
        const float mn_lo = fmaxf(m_lo, mx_lo);
        const float mn_hi = fmaxf(m_hi, mx_hi);
        const float al_lo = __expf(m_lo - mn_lo);
        const float al_hi = __expf(m_hi - mn_hi);
        m_lo = mn_lo; m_hi = mn_hi;

        float sum_lo = 0.f, sum_hi = 0.f;
        uint32_t aph[4][4], apl[4][4];
        #pragma unroll
        for (int kt2 = 0; kt2 < 4; kt2++) {
            float p[2][4];
            #pragma unroll
            for (int half = 0; half < 2; half++) {
                const int nt = 2 * kt2 + half;
                p[half][0] = __expf(sacc[nt][0] - mn_lo);
                p[half][1] = __expf(sacc[nt][1] - mn_lo);
                p[half][2] = __expf(sacc[nt][2] - mn_hi);
                p[half][3] = __expf(sacc[nt][3] - mn_hi);
                sum_lo += p[half][0] + p[half][1];
                sum_hi += p[half][2] + p[half][3];
            }
            #pragma unroll
            for (int half = 0; half < 2; half++) {
                __nv_bfloat16 h0, l0, h1, l1, h2, l2, h3, l3;
                split_bf16(p[half][0], h0, l0);
                split_bf16(p[half][1], h1, l1);
                split_bf16(p[half][2], h2, l2);
                split_bf16(p[half][3], h3, l3);
                aph[kt2][0 + 2 * half] = pack_bf16(h0, h1);
                aph[kt2][1 + 2 * half] = pack_bf16(h2, h3);
                apl[kt2][0 + 2 * half] = pack_bf16(l0, l1);
                apl[kt2][1 + 2 * half] = pack_bf16(l2, l3);
            }
        }
        #pragma unroll
        for (int off = 1; off < 4; off <<= 1) {
            sum_lo += __shfl_xor_sync(0xffffffffu, sum_lo, off);
            sum_hi += __shfl_xor_sync(0xffffffffu, sum_hi, off);
        }
        l_lo = l_lo * al_lo + sum_lo;
        l_hi = l_hi * al_hi + sum_hi;
        #pragma unroll
        for (int dt = 0; dt < 16; dt++) {
            o[dt][0] *= al_lo; o[dt][1] *= al_lo;
            o[dt][2] *= al_hi; o[dt][3] *= al_hi;
        }

        // ---- O += P V (3-pass, V via ldmatrix.trans) ----
        #pragma unroll
        for (int kt2 = 0; kt2 < 4; kt2++) {
            #pragma unroll
            for (int dp = 0; dp < 8; dp++) {
                uint32_t vh[4], vl[4];
                const uint32_t vo = offkv(kt2 * 16 + v_r, 2 * dp + v_co);
                ldsm4t(vh[0], vh[1], vh[2], vh[3], stb + VH_OFF + vo);
                ldsm4t(vl[0], vl[1], vl[2], vl[3], stb + VL_OFF + vo);
                #pragma unroll
                for (int d2 = 0; d2 < 2; d2++) {
                    const int dt = 2 * dp + d2;
                    uint32_t bh[2] = { vh[d2 * 2], vh[d2 * 2 + 1] };
                    uint32_t bl[2] = { vl[d2 * 2], vl[d2 * 2 + 1] };
                    mma_bf16(o[dt], aph[kt2], bh);
                    mma_bf16(o[dt], apl[kt2], bh);
                    mma_bf16(o[dt], aph[kt2], bl);
                }
            }
        }

        __syncthreads();
        if (t + 2 < ntiles) { load_kv(t & 1, t + 2); }
        CP_COMMIT();
    }

    // ---- epilogue: normalize + split-bf16 store ----
    const float inv_lo = 1.f / l_lo;
    const float inv_hi = 1.f / l_hi;
    const size_t ro_lo = ((size_t)(tb + row_lo) * NH + h) * HD;
    const size_t ro_hi = ro_lo + (size_t)8 * NH * HD;
    #pragma unroll
    for (int dt = 0; dt < 16; dt++) {
        const int c = dt * 8 + col_l;
        float f0 = o[dt][0] * inv_lo, f1 = o[dt][1] * inv_lo;
        float f2 = o[dt][2] * inv_hi, f3 = o[dt][3] * inv_hi;
        __nv_bfloat16 h0, l0, h1, l1, h2, l2, h3, l3;
        split_bf16(f0, h0, l0);
        split_bf16(f1, h1, l1);
        split_bf16(f2, h2, l2);
        split_bf16(f3, h3, l3);
        *(uint32_t*)(g_oh + ro_lo + c) = pack_bf16(h0, h1);
        *(uint32_t*)(g_ol + ro_lo + c) = pack_bf16(l0, l1);
        *(uint32_t*)(g_oh + ro_hi + c) = pack_bf16(h2, h3);
        *(uint32_t*)(g_ol + ro_hi + c) = pack_bf16(l2, l3);
    }
}

// ---------------- launch ----------------------------------------------------
extern "C" void kernel_launch(void* const* d_in, const int* in_sizes, int n_in,
                              void* d_out, int out_size)
{
    const float* x    = (const float*)d_in[0];
    const float* fcos = (const float*)d_in[2];
    const float* fsin = (const float*)d_in[3];
    const float* wq   = (const float*)d_in[6];
    const float* wk   = (const float*)d_in[7];
    const float* wv   = (const float*)d_in[8];
    const float* wo   = (const float*)d_in[9];
    float* out        = (float*)d_out;

    float *q, *k, *v;
    cudaGetSymbolAddress((void**)&q, g_q);
    cudaGetSymbolAddress((void**)&k, g_k);
    cudaGetSymbolAddress((void**)&v, g_v);
    __nv_bfloat16 *xh, *xl, *oh, *ol;
    __nv_bfloat16 *wqh, *wql, *wkh, *wkl, *wvh, *wvl, *woh, *wol;
    cudaGetSymbolAddress((void**)&xh, g_xh);
    cudaGetSymbolAddress((void**)&xl, g_xl);
    cudaGetSymbolAddress((void**)&oh, g_oh);
    cudaGetSymbolAddress((void**)&ol, g_ol);
    cudaGetSymbolAddress((void**)&wqh, g_wqt_h);
    cudaGetSymbolAddress((void**)&wql, g_wqt_l);
    cudaGetSymbolAddress((void**)&wkh, g_wkt_h);
    cudaGetSymbolAddress((void**)&wkl, g_wkt_l);
    cudaGetSymbolAddress((void**)&wvh, g_wvt_h);
    cudaGetSymbolAddress((void**)&wvl, g_wvt_l);
    cudaGetSymbolAddress((void**)&woh, g_wot_h);
    cudaGetSymbolAddress((void**)&wol, g_wot_l);

    cudaFuncSetAttribute(gemm_hmma, cudaFuncAttributeMaxDynamicSharedMemorySize, GEMM_SMEM);
    cudaFuncSetAttribute(attn_hmma, cudaFuncAttributeMaxDynamicSharedMemorySize, ATTN_SMEM);

    // 0) operand conversion
    conv_split_kernel<<<(T_ * DIM / 4 + 255) / 256, 256>>>(x, xh, xl, T_ * DIM / 4);
    wconv_kernel<<<dim3(DIM / 32, DIM / 32), dim3(32, 8)>>>(wq, wqh, wql, DIM);
    wconv_kernel<<<dim3((NKV * HD) / 32, DIM / 32), dim3(32, 8)>>>(wk, wkh, wkl, NKV * HD);
    wconv_kernel<<<dim3((NKV * HD) / 32, DIM / 32), dim3(32, 8)>>>(wv, wvh, wvl, NKV * HD);
    wconv_kernel<<<dim3(DIM / 32, DIM / 32), dim3(32, 8)>>>(wo, woh, wol, DIM);

    // 1) projections (HMMA split-bf16)
    gemm_hmma<<<dim3(DIM / 128, T_ / 128), 256, GEMM_SMEM>>>(xh, xl, wqh, wql, q, DIM);
    gemm_hmma<<<dim3((NKV * HD) / 128, T_ / 128), 256, GEMM_SMEM>>>(xh, xl, wkh, wkl, k, NKV * HD);
    gemm_hmma<<<dim3((NKV * HD) / 128, T_ / 128), 256, GEMM_SMEM>>>(xh, xl, wvh, wvl, v, NKV * HD);

    // 2) RoPE + split to bf16 h/l
    {
        int total = T_ * (NH + 2 * NKV) * (HD / 2);
        prep_kernel<<<(total + 255) / 256, 256>>>(fcos, fsin);
    }

    // 3) attention (HMMA split-bf16 flash)
    attn_hmma<<<dim3(S_ / 128, NH, B_), 256, ATTN_SMEM>>>();

    // 4) output projection (reads split O directly)
    gemm_hmma<<<dim3(DIM / 128, T_ / 128), 256, GEMM_SMEM>>>(oh, ol, woh, wol, out, DIM);
}

// round 5
// speedup vs baseline: 2.9888x; 1.5062x over previous
#include <cuda_runtime.h>
#include <cuda_fp16.h>
#include <cstdint>
#include <math.h>

#define DIM 4096
#define NH  32
#define NKV 8
#define HD  128
#define B_  2
#define S_  2048
#define T_  (B_*S_)          // 4096 tokens
#define NREP 4

// ---------------- scratch (device globals; no cudaMalloc allowed) ----------
__device__ float g_q[(size_t)T_ * NH  * HD];
__device__ float g_k[(size_t)T_ * NKV * HD];
__device__ float g_v[(size_t)T_ * NKV * HD];

// split-fp16 operands (A-side hi/lo; weights single fp16)
__device__ __half g_xh[(size_t)T_ * DIM];
__device__ __half g_xl[(size_t)T_ * DIM];
__device__ __half g_oh[(size_t)T_ * DIM];
__device__ __half g_ol[(size_t)T_ * DIM];
__device__ __half g_qh[(size_t)T_ * NH * HD];
__device__ __half g_ql[(size_t)T_ * NH * HD];
__device__ __half g_kh[(size_t)T_ * NKV * HD];
__device__ __half g_kl[(size_t)T_ * NKV * HD];
__device__ __half g_vh[(size_t)T_ * NKV * HD];
__device__ __half g_wqt[(size_t)DIM * DIM];
__device__ __half g_wkt[(size_t)(NKV*HD) * DIM];
__device__ __half g_wvt[(size_t)(NKV*HD) * DIM];
__device__ __half g_wot[(size_t)DIM * DIM];

// ---------------- low-level helpers (sm_103 base-target safe) --------------
__device__ __forceinline__ uint32_t smem_u32(const void* p) {
    uint32_t a;
    asm("{ .reg .u64 t; cvta.to.shared.u64 t, %1; cvt.u32.u64 %0, t; }"
        : "=r"(a) : "l"(p));
    return a;
}
__device__ __forceinline__ void cp_async16(uint32_t dst, const void* src) {
    asm volatile("cp.async.cg.shared.global [%0], [%1], 16;"
                 :: "r"(dst), "l"(src));
}
#define CP_COMMIT() asm volatile("cp.async.commit_group;" ::: "memory")
#define CP_WAIT(n)  asm volatile("cp.async.wait_group %0;" :: "n"(n) : "memory")

__device__ __forceinline__ void ldsm4(uint32_t& r0, uint32_t& r1,
                                      uint32_t& r2, uint32_t& r3, uint32_t a) {
    asm volatile("ldmatrix.sync.aligned.m8n8.x4.shared.b16 {%0,%1,%2,%3}, [%4];"
                 : "=r"(r0), "=r"(r1), "=r"(r2), "=r"(r3) : "r"(a));
}
__device__ __forceinline__ void ldsm4t(uint32_t& r0, uint32_t& r1,
                                       uint32_t& r2, uint32_t& r3, uint32_t a) {
    asm volatile("ldmatrix.sync.aligned.m8n8.x4.trans.shared.b16 {%0,%1,%2,%3}, [%4];"
                 : "=r"(r0), "=r"(r1), "=r"(r2), "=r"(r3) : "r"(a));
}
__device__ __forceinline__ void mma_f16(float* c, const uint32_t* a,
                                        const uint32_t* b) {
    asm volatile(
        "mma.sync.aligned.m16n8k16.row.col.f32.f16.f16.f32 "
        "{%0,%1,%2,%3}, {%4,%5,%6,%7}, {%8,%9}, {%0,%1,%2,%3};"
        : "+f"(c[0]), "+f"(c[1]), "+f"(c[2]), "+f"(c[3])
        : "r"(a[0]), "r"(a[1]), "r"(a[2]), "r"(a[3]), "r"(b[0]), "r"(b[1]));
}

// ---------------- split-fp16 conversion -------------------------------------
__device__ __forceinline__ void split_f16(float x, __half& h, __half& l)
{
    h = __float2half_rn(x);
    l = __float2half_rn(x - __half2float(h));
}
__device__ __forceinline__ uint32_t pack_f16(__half lo, __half hi)
{
    __half2 v;
    v.x = lo; v.y = hi;
    return *(uint32_t*)&v;
}

__global__ void conv_split_kernel(const float* __restrict__ X,
                                  __half* __restrict__ H,
                                  __half* __restrict__ L, int n4)
{
    int i = blockIdx.x * blockDim.x + threadIdx.x;
    if (i >= n4) return;
    float4 v = *(const float4*)(X + (size_t)i * 4);
    __half h[4], l[4];
    split_f16(v.x, h[0], l[0]);
    split_f16(v.y, h[1], l[1]);
    split_f16(v.z, h[2], l[2]);
    split_f16(v.w, h[3], l[3]);
    *(uint2*)(H + (size_t)i * 4) = *(uint2*)h;
    *(uint2*)(L + (size_t)i * 4) = *(uint2*)l;
}

// transpose + convert: W[K=DIM, N] -> T[N, DIM] fp16
__global__ void wconv_kernel(const float* __restrict__ W,
                             __half* __restrict__ H, int N)
{
    __shared__ float t[32][33];
    const int n0 = blockIdx.x * 32;
    const int k0 = blockIdx.y * 32;
    const int tx = threadIdx.x;
    const int ty = threadIdx.y;
    #pragma unroll
    for (int i = 0; i < 4; i++)
        t[ty + 8 * i][tx] = W[(size_t)(k0 + ty + 8 * i) * N + n0 + tx];
    __syncthreads();
    #pragma unroll
    for (int i = 0; i < 4; i++) {
        float v = t[tx][ty + 8 * i];
        H[(size_t)(n0 + ty + 8 * i) * DIM + k0 + tx] = __float2half_rn(v);
    }
}

// ---------------- prep: RoPE (q,k) + split/convert to fp16 ------------------
__global__ void prep_kernel(const float* __restrict__ fcos,
                            const float* __restrict__ fsin)
{
    int idx = blockIdx.x * blockDim.x + threadIdx.x;
    const int total = T_ * (NH + 2 * NKV) * (HD / 2);
    if (idx >= total) return;
    int d    = idx % (HD / 2);
    int rest = idx / (HD / 2);
    int hh   = rest % (NH + 2 * NKV);
    int t    = rest / (NH + 2 * NKV);
    int s    = t % S_;

    if (hh < NH + NKV) {
        const float* src;
        __half *H, *L;
        size_t off;
        if (hh < NH) {
            off = ((size_t)t * NH + hh) * HD + 2 * d;
            src = g_q + off; H = g_qh; L = g_ql;
        } else {
            off = ((size_t)t * NKV + (hh - NH)) * HD + 2 * d;
            src = g_k + off; H = g_kh; L = g_kl;
        }
        float c  = fcos[s * (HD / 2) + d];
        float sn = fsin[s * (HD / 2) + d];
        float a0 = src[0], a1 = src[1];
        float x0 = a0 * c - a1 * sn;
        float x1 = a0 * sn + a1 * c;
        __half h0, l0, h1, l1;
        split_f16(x0, h0, l0);
        split_f16(x1, h1, l1);
        *(uint32_t*)(H + off) = pack_f16(h0, h1);
        *(uint32_t*)(L + off) = pack_f16(l0, l1);
    } else {
        size_t off = ((size_t)t * NKV + (hh - NH - NKV)) * HD + 2 * d;
        __half h0 = __float2half_rn(g_v[off]);
        __half h1 = __float2half_rn(g_v[off + 1]);
        *(uint32_t*)(g_vh + off) = pack_f16(h0, h1);
    }
}

// ---------------- HMMA 2-pass split-fp16 GEMM --------------------------------
// C[M,N] = (Ah + Al) * B^T, B rows are [N,K] fp16. 2 passes: AhB + AlB.
#define GK       DIM
#define GCHUNKS  (GK / 32)
#define OPB      8192               // 128 rows x 4 chunks x 16B
#define STAGEB   (3 * OPB)          // 24 KB per stage (Ah, Al, B)
#define NSTAGE   3
#define GEMM_SMEM (NSTAGE * STAGEB) // 72 KB -> 2 CTAs/SM

__device__ __forceinline__ uint32_t chunk_off(int row, int kg) {
    return (uint32_t)(kg * 128 + ((row + 2 * kg) & 127)) * 16u;
}

__global__ __launch_bounds__(256, 2) void gemm_hmma(
    const __half* __restrict__ Ah, const __half* __restrict__ Al,
    const __half* __restrict__ B,
    float* __restrict__ C, int N)
{
    extern __shared__ char smg[];
    const uint32_t sbase = smem_u32(smg);

    const int tid = threadIdx.x;
    const int wid = tid >> 5;
    const int lid = tid & 31;
    const int wm  = wid >> 2;
    const int wn  = wid & 3;
    const int m0  = blockIdx.y * 128;
    const int n0  = blockIdx.x * 128;

    const int lkg = tid & 3;
    const int lr  = tid >> 2;

    auto load_stage = [&](int stage, int kc) {
        const uint32_t sb = sbase + stage * STAGEB;
        const size_t koff = (size_t)kc * 32 + lkg * 8;
        #pragma unroll
        for (int i = 0; i < 2; i++) {
            const int r = lr + i * 64;
            const uint32_t co = chunk_off(r, lkg);
            const size_t ga = (size_t)(m0 + r) * GK + koff;
            const size_t gb = (size_t)(n0 + r) * GK + koff;
            cp_async16(sb + 0 * OPB + co, Ah + ga);
            cp_async16(sb + 1 * OPB + co, Al + ga);
            cp_async16(sb + 2 * OPB + co, B + gb);
        }
    };

    float acc[4][4][4];
    #pragma unroll
    for (int i = 0; i < 4; i++)
        #pragma unroll
        for (int j = 0; j < 4; j++)
            #pragma unroll
            for (int k = 0; k < 4; k++) acc[i][j][k] = 0.f;

    const int sel  = lid >> 3;
    const int lsub = lid & 7;
    const int a_mo = lsub + ((sel & 1) << 3);
    const int a_kg = sel >> 1;
    const int b_no = lsub + ((sel >> 1) << 3);
    const int b_kg = sel & 1;

    load_stage(0, 0); CP_COMMIT();
    load_stage(1, 1); CP_COMMIT();

    for (int kc = 0; kc < GCHUNKS; kc++) {
        const int s = kc % NSTAGE;
        CP_WAIT(1);
        __syncthreads();

        if (kc + 2 < GCHUNKS) load_stage((kc + 2) % NSTAGE, kc + 2);
        CP_COMMIT();

        const uint32_t sb = sbase + s * STAGEB;

        #pragma unroll
        for (int ks = 0; ks < 2; ks++) {
            const int kgA = ks * 2 + a_kg;
            const int kgB = ks * 2 + b_kg;

            uint32_t afh[4][4], afl[4][4];
            #pragma unroll
            for (int mt = 0; mt < 4; mt++) {
                const int m = wm * 64 + mt * 16 + a_mo;
                const uint32_t co = chunk_off(m, kgA);
                ldsm4(afh[mt][0], afh[mt][1], afh[mt][2], afh[mt][3],
                      sb + 0 * OPB + co);
                ldsm4(afl[mt][0], afl[mt][1], afl[mt][2], afl[mt][3],
                      sb + 1 * OPB + co);
            }
            uint32_t bf[2][4];
            #pragma unroll
            for (int nt2 = 0; nt2 < 2; nt2++) {
                const int n = wn * 32 + nt2 * 16 + b_no;
                const uint32_t co = chunk_off(n, kgB);
                ldsm4(bf[nt2][0], bf[nt2][1], bf[nt2][2], bf[nt2][3],
                      sb + 2 * OPB + co);
            }
            #pragma unroll
            for (int mt = 0; mt < 4; mt++)
                #pragma unroll
                for (int nt = 0; nt < 4; nt++) {
                    uint32_t b2[2] = { bf[nt >> 1][(nt & 1) << 1],
                                       bf[nt >> 1][((nt & 1) << 1) + 1] };
                    mma_f16(acc[mt][nt], afh[mt], b2);
                    mma_f16(acc[mt][nt], afl[mt], b2);
                }
        }
    }

    const int crow = lid >> 2;
    const int ccol = (lid & 3) * 2;
    #pragma unroll
    for (int mt = 0; mt < 4; mt++) {
        const int r0 = m0 + wm * 64 + mt * 16 + crow;
        #pragma unroll
        for (int nt = 0; nt < 4; nt++) {
            const int c0 = n0 + wn * 32 + nt * 8 + ccol;
            *(float2*)(C + (size_t)r0 * N + c0) =
                make_float2(acc[mt][nt][0], acc[mt][nt][1]);
            *(float2*)(C + (size_t)(r0 + 8) * N + c0) =
                make_float2(acc[mt][nt][2], acc[mt][nt][3]);
        }
    }
}

// ---------------- HMMA split-fp16 flash attention ---------------------------
// CTA: 128 q rows x one (b, head). S = QK^T 3-pass; O += PV 1-pass (P,V fp16).
#define SQH_OFF 0
#define SQL_OFF 32768
#define STG_OFF 65536
#define STG_SZ  49152              // Kh + Kl + Vh
#define KH_OFF  0
#define KL_OFF  16384
#define VH_OFF  32768
#define ATTN_SMEM (STG_OFF + 2 * STG_SZ)   // 160 KB

__device__ __forceinline__ uint32_t offq(int r, int c) {
    return (uint32_t)(c * 128 + ((r + 2 * c) & 127)) * 16u;
}
__device__ __forceinline__ uint32_t offkv(int r, int c) {
    return (uint32_t)(c * 64 + ((r + 2 * c) & 63)) * 16u;
}

__global__ __launch_bounds__(256, 1) void attn_hmma()
{
    extern __shared__ char sma[];
    const uint32_t sb = smem_u32(sma);

    const int tid = threadIdx.x;
    const int wid = tid >> 5;
    const int lid = tid & 31;
    const int bx  = blockIdx.x;
    const int h   = blockIdx.y;
    const int bz  = blockIdx.z;
    const int g   = h >> 2;
    const int qm0 = bx * 128;
    const int tb  = bz * S_;
    const int ntiles = 2 * (bx + 1);

    const int sel  = lid >> 3;
    const int lsub = lid & 7;
    const int a_r  = wid * 16 + lsub + ((sel & 1) << 3);
    const int a_co = sel >> 1;
    const int b_r  = lsub + ((sel >> 1) << 3);
    const int b_co = sel & 1;
    const int v_r  = lsub + ((sel & 1) << 3);
    const int v_co = sel >> 1;

    const int lc = tid & 15;
    const int lr = tid >> 4;

    // Q (once): 128 rows x 16 chunks x {h,l}
    {
        #pragma unroll
        for (int i = 0; i < 8; i++) {
            const int r = lr + 16 * i;
            const size_t go = ((size_t)(tb + qm0 + r) * NH + h) * HD + lc * 8;
            const uint32_t o = offq(r, lc);
            cp_async16(sb + SQH_OFF + o, g_qh + go);
            cp_async16(sb + SQL_OFF + o, g_ql + go);
        }
    }
    auto load_kv = [&](int stage, int t) {
        const uint32_t st = sb + STG_OFF + stage * STG_SZ;
        const int j0 = t * 64;
        #pragma unroll
        for (int i = 0; i < 4; i++) {
            const int r = lr + 16 * i;
            const size_t go = ((size_t)(tb + j0 + r) * NKV + g) * HD + lc * 8;
            const uint32_t o = offkv(r, lc);
            cp_async16(st + KH_OFF + o, g_kh + go);
            cp_async16(st + KL_OFF + o, g_kl + go);
            cp_async16(st + VH_OFF + o, g_vh + go);
        }
    };

    load_kv(0, 0); CP_COMMIT();
    if (ntiles > 1) { load_kv(1, 1); }
    CP_COMMIT();

    float o[16][4];
    #pragma unroll
    for (int i = 0; i < 16; i++)
        #pragma unroll
        for (int j = 0; j < 4; j++) o[i][j] = 0.f;
    float m_lo = -1e30f, m_hi = -1e30f;
    float l_lo = 0.f, l_hi = 0.f;
    const float scale = 0.08838834764831843f;
    const int row_lo = qm0 + wid * 16 + (lid >> 2);
    const int col_l  = (lid & 3) * 2;

    for (int t = 0; t < ntiles; t++) {
        if (t + 1 < ntiles) { CP_WAIT(1); } else { CP_WAIT(0); }
        __syncthreads();

        const uint32_t stb = sb + STG_OFF + (t & 1) * STG_SZ;
        const bool masked = (t >= 2 * bx);
        const int j0 = t * 64;

        // ---- S = Q K^T (3-pass fp16) ----
        float sacc[8][4];
        #pragma unroll
        for (int i = 0; i < 8; i++)
            #pragma unroll
            for (int j = 0; j < 4; j++) sacc[i][j] = 0.f;

        #pragma unroll
        for (int kt = 0; kt < 8; kt++) {
            uint32_t qh[4], ql[4];
            const uint32_t qo = offq(a_r, 2 * kt + a_co);
            ldsm4(qh[0], qh[1], qh[2], qh[3], sb + SQH_OFF + qo);
            ldsm4(ql[0], ql[1], ql[2], ql[3], sb + SQL_OFF + qo);
            uint32_t kh[4][4], kl[4][4];
            #pragma unroll
            for (int np = 0; np < 4; np++) {
                const uint32_t ko = offkv(np * 16 + b_r, 2 * kt + b_co);
                ldsm4(kh[np][0], kh[np][1], kh[np][2], kh[np][3],
                      stb + KH_OFF + ko);
                ldsm4(kl[np][0], kl[np][1], kl[np][2], kl[np][3],
                      stb + KL_OFF + ko);
            }
            #pragma unroll
            for (int nt = 0; nt < 8; nt++) {
                uint32_t bh[2] = { kh[nt >> 1][(nt & 1) << 1],
                                   kh[nt >> 1][((nt & 1) << 1) + 1] };
                uint32_t bl[2] = { kl[nt >> 1][(nt & 1) << 1],
                                   kl[nt >> 1][((nt & 1) << 1) + 1] };
                mma_f16(sacc[nt], qh, bh);
                mma_f16(sacc[nt], ql, bh);
                mma_f16(sacc[nt], qh, bl);
            }
        }

        // ---- scale + causal mask ----
        if (masked) {
            #pragma unroll
            for (int nt = 0; nt < 8; nt++) {
                const int c0 = j0 + nt * 8 + col_l;
                sacc[nt][0] = (c0     <= row_lo)     ? sacc[nt][0] * scale : -1e30f;
                sacc[nt][1] = (c0 + 1 <= row_lo)     ? sacc[nt][1] * scale : -1e30f;
                sacc[nt][2] = (c0     <= row_lo + 8) ? sacc[nt][2] * scale : -1e30f;
                sacc[nt][3] = (c0 + 1 <= row_lo + 8) ? sacc[nt][3] * scale : -1e30f;
            }
        } else {
            #pragma unroll
            for (int nt = 0; nt < 8; nt++)
                #pragma unroll
                for (int e = 0; e < 4; e++) sacc[nt][e] *= scale;
        }

        // ---- online softmax ----
        float mx_lo = -1e30f, mx_hi = -1e30f;
        #pragma unroll
        for (int nt = 0; nt < 8; nt++) {
            mx_lo = fmaxf(mx_lo, fmaxf(sacc[nt][0], sacc[nt][1]));
            mx_hi = fmaxf(mx_hi, fmaxf(sacc[nt][2], sacc[nt][3]));
        }
        #pragma unroll
        for (int off = 1; off < 4; off <<= 1) {
            mx_lo = fmaxf(mx_lo, __shfl_xor_sync(0xffffffffu, mx_lo, off));
            mx_hi = fmaxf(mx_hi, __shfl_xor_sync(0xffffffffu, mx_hi, off));
        }
        const float mn_lo = fmaxf(m_lo, mx_lo);
        const float mn_hi = fmaxf(m_hi, mx_hi);
        const float al_lo = __expf(m_lo - mn_lo);
        const float al_hi = __expf(m_hi - mn_hi);
        m_lo = mn_lo; m_hi = mn_hi;

        float sum_lo = 0.f, sum_hi = 0.f;
        uint32_t aph[4][4];
        #pragma unroll
        for (int kt2 = 0; kt2 < 4; kt2++) {
            float p[2][4];
            #pragma unroll
            for (int half = 0; half < 2; half++) {
                const int nt = 2 * kt2 + half;
                p[half][0] = __expf(sacc[nt][0] - mn_lo);
                p[half][1] = __expf(sacc[nt][1] - mn_lo);
                p[half][2] = __expf(sacc[nt][2] - mn_hi);
                p[half][3] = __expf(sacc[nt][3] - mn_hi);
                sum_lo += p[half][0] + p[half][1];
                sum_hi += p[half][2] + p[half][3];
            }
            #pragma unroll
            for (int half = 0; half < 2; half++) {
                aph[kt2][0 + 2 * half] = pack_f16(__float2half_rn(p[half][0]),
                                                  __float2half_rn(p[half][1]));
                aph[kt2][1 + 2 * half] = pack_f16(__float2half_rn(p[half][2]),
                                                  __float2half_rn(p[half][3]));
            }
        }
        #pragma unroll
        for (int off = 1; off < 4; off <<= 1) {
            sum_lo += __shfl_xor_sync(0xffffffffu, sum_lo, off);
            sum_hi += __shfl_xor_sync(0xffffffffu, sum_hi, off);
        }
        l_lo = l_lo * al_lo + sum_lo;
        l_hi = l_hi * al_hi + sum_hi;
        #pragma unroll
        for (int dt = 0; dt < 16; dt++) {
            o[dt][0] *= al_lo; o[dt][1] *= al_lo;
            o[dt][2] *= al_hi; o[dt][3] *= al_hi;
        }

        // ---- O += P V (1-pass fp16) ----
        #pragma unroll
        for (int kt2 = 0; kt2 < 4; kt2++) {
            #pragma unroll
            for (int dp = 0; dp < 8; dp++) {
                uint32_t vh[4];
                const uint32_t vo = offkv(kt2 * 16 + v_r, 2 * dp + v_co);
                ldsm4t(vh[0], vh[1], vh[2], vh[3], stb + VH_OFF + vo);
                #pragma unroll
                for (int d2 = 0; d2 < 2; d2++) {
                    const int dt = 2 * dp + d2;
                    uint32_t bh[2] = { vh[d2 * 2], vh[d2 * 2 + 1] };
                    mma_f16(o[dt], aph[kt2], bh);
                }
            }
        }

        __syncthreads();
        if (t + 2 < ntiles) { load_kv(t & 1, t + 2); }
        CP_COMMIT();
    }

    // ---- epilogue: normalize + split-fp16 store ----
    const float inv_lo = 1.f / l_lo;
    const float inv_hi = 1.f / l_hi;
    const size_t ro_lo = ((size_t)(tb + row_lo) * NH + h) * HD;
    const size_t ro_hi = ro_lo + (size_t)8 * NH * HD;
    #pragma unroll
    for (int dt = 0; dt < 16; dt++) {
        const int c = dt * 8 + col_l;
        float f0 = o[dt][0] * inv_lo, f1 = o[dt][1] * inv_lo;
        float f2 = o[dt][2] * inv_hi, f3 = o[dt][3] * inv_hi;
        __half h0, l0, h1, l1, h2, l2, h3, l3;
        split_f16(f0, h0, l0);
        split_f16(f1, h1, l1);
        split_f16(f2, h2, l2);
        split_f16(f3, h3, l3);
        *(uint32_t*)(g_oh + ro_lo + c) = pack_f16(h0, h1);
        *(uint32_t*)(g_ol + ro_lo + c) = pack_f16(l0, l1);
        *(uint32_t*)(g_oh + ro_hi + c) = pack_f16(h2, h3);
        *(uint32_t*)(g_ol + ro_hi + c) = pack_f16(l2, l3);
    }
}

// ---------------- launch ----------------------------------------------------
extern "C" void kernel_launch(void* const* d_in, const int* in_sizes, int n_in,
                              void* d_out, int out_size)
{
    const float* x    = (const float*)d_in[0];
    const float* fcos = (const float*)d_in[2];
    const float* fsin = (const float*)d_in[3];
    const float* wq   = (const float*)d_in[6];
    const float* wk   = (const float*)d_in[7];
    const float* wv   = (const float*)d_in[8];
    const float* wo   = (const float*)d_in[9];
    float* out        = (float*)d_out;

    float *q, *k, *v;
    cudaGetSymbolAddress((void**)&q, g_q);
    cudaGetSymbolAddress((void**)&k, g_k);
    cudaGetSymbolAddress((void**)&v, g_v);
    __half *xh, *xl, *oh, *ol, *wqt, *wkt, *wvt, *wot;
    cudaGetSymbolAddress((void**)&xh, g_xh);
    cudaGetSymbolAddress((void**)&xl, g_xl);
    cudaGetSymbolAddress((void**)&oh, g_oh);
    cudaGetSymbolAddress((void**)&ol, g_ol);
    cudaGetSymbolAddress((void**)&wqt, g_wqt);
    cudaGetSymbolAddress((void**)&wkt, g_wkt);
    cudaGetSymbolAddress((void**)&wvt, g_wvt);
    cudaGetSymbolAddress((void**)&wot, g_wot);

    cudaFuncSetAttribute(gemm_hmma, cudaFuncAttributeMaxDynamicSharedMemorySize, GEMM_SMEM);
    cudaFuncSetAttribute(attn_hmma, cudaFuncAttributeMaxDynamicSharedMemorySize, ATTN_SMEM);

    // 0) operand conversion
    conv_split_kernel<<<(T_ * DIM / 4 + 255) / 256, 256>>>(x, xh, xl, T_ * DIM / 4);
    wconv_kernel<<<dim3(DIM / 32, DIM / 32), dim3(32, 8)>>>(wq, wqt, DIM);
    wconv_kernel<<<dim3((NKV * HD) / 32, DIM / 32), dim3(32, 8)>>>(wk, wkt, NKV * HD);
    wconv_kernel<<<dim3((NKV * HD) / 32, DIM / 32), dim3(32, 8)>>>(wv, wvt, NKV * HD);
    wconv_kernel<<<dim3(DIM / 32, DIM / 32), dim3(32, 8)>>>(wo, wot, DIM);

    // 1) projections (HMMA 2-pass split-fp16)
    gemm_hmma<<<dim3(DIM / 128, T_ / 128), 256, GEMM_SMEM>>>(xh, xl, wqt, q, DIM);
    gemm_hmma<<<dim3((NKV * HD) / 128, T_ / 128), 256, GEMM_SMEM>>>(xh, xl, wkt, k, NKV * HD);
    gemm_hmma<<<dim3((NKV * HD) / 128, T_ / 128), 256, GEMM_SMEM>>>(xh, xl, wvt, v, NKV * HD);

    // 2) RoPE + split/convert to fp16
    {
        int total = T_ * (NH + 2 * NKV) * (HD / 2);
        prep_kernel<<<(total + 255) / 256, 256>>>(fcos, fsin);
    }

    // 3) attention (HMMA split-fp16 flash)
    attn_hmma<<<dim3(S_ / 128, NH, B_), 256, ATTN_SMEM>>>();

    // 4) output projection
    gemm_hmma<<<dim3(DIM / 128, T_ / 128), 256, GEMM_SMEM>>>(oh, ol, wot, out, DIM);
}

// round 6
// speedup vs baseline: 3.1667x; 1.0595x over previous
#include <cuda_runtime.h>
#include <cuda_fp16.h>
#include <cstdint>
#include <math.h>

#define DIM 4096
#define NH  32
#define NKV 8
#define HD  128
#define B_  2
#define S_  2048
#define T_  (B_*S_)          // 4096 tokens
#define NREP 4
#define NQKV 6144            // NH*HD + 2*NKV*HD

// ---------------- scratch (device globals; no cudaMalloc allowed) ----------
__device__ __half g_xh[(size_t)T_ * DIM];
__device__ __half g_xl[(size_t)T_ * DIM];
__device__ __half g_oh[(size_t)T_ * DIM];
__device__ __half g_ol[(size_t)T_ * DIM];
__device__ __half g_qh[(size_t)T_ * NH * HD];
__device__ __half g_ql[(size_t)T_ * NH * HD];
__device__ __half g_kh[(size_t)T_ * NKV * HD];
__device__ __half g_kl[(size_t)T_ * NKV * HD];
__device__ __half g_vh[(size_t)T_ * NKV * HD];
__device__ __half g_wqkv[(size_t)NQKV * DIM];   // [wq | wk | wv] transposed
__device__ __half g_wot[(size_t)DIM * DIM];

// ---------------- low-level helpers (sm_103 base-target safe) --------------
__device__ __forceinline__ uint32_t smem_u32(const void* p) {
    uint32_t a;
    asm("{ .reg .u64 t; cvta.to.shared.u64 t, %1; cvt.u32.u64 %0, t; }"
        : "=r"(a) : "l"(p));
    return a;
}
__device__ __forceinline__ void cp_async16(uint32_t dst, const void* src) {
    asm volatile("cp.async.cg.shared.global [%0], [%1], 16;"
                 :: "r"(dst), "l"(src));
}
#define CP_COMMIT() asm volatile("cp.async.commit_group;" ::: "memory")
#define CP_WAIT(n)  asm volatile("cp.async.wait_group %0;" :: "n"(n) : "memory")

__device__ __forceinline__ void ldsm4(uint32_t& r0, uint32_t& r1,
                                      uint32_t& r2, uint32_t& r3, uint32_t a) {
    asm volatile("ldmatrix.sync.aligned.m8n8.x4.shared.b16 {%0,%1,%2,%3}, [%4];"
                 : "=r"(r0), "=r"(r1), "=r"(r2), "=r"(r3) : "r"(a));
}
__device__ __forceinline__ void ldsm4t(uint32_t& r0, uint32_t& r1,
                                       uint32_t& r2, uint32_t& r3, uint32_t a) {
    asm volatile("ldmatrix.sync.aligned.m8n8.x4.trans.shared.b16 {%0,%1,%2,%3}, [%4];"
                 : "=r"(r0), "=r"(r1), "=r"(r2), "=r"(r3) : "r"(a));
}
__device__ __forceinline__ void mma_f16(float* c, const uint32_t* a,
                                        const uint32_t* b) {
    asm volatile(
        "mma.sync.aligned.m16n8k16.row.col.f32.f16.f16.f32 "
        "{%0,%1,%2,%3}, {%4,%5,%6,%7}, {%8,%9}, {%0,%1,%2,%3};"
        : "+f"(c[0]), "+f"(c[1]), "+f"(c[2]), "+f"(c[3])
        : "r"(a[0]), "r"(a[1]), "r"(a[2]), "r"(a[3]), "r"(b[0]), "r"(b[1]));
}

// ---------------- split-fp16 conversion -------------------------------------
__device__ __forceinline__ void split_f16(float x, __half& h, __half& l)
{
    h = __float2half_rn(x);
    l = __float2half_rn(x - __half2float(h));
}
__device__ __forceinline__ uint32_t pack_f16(__half lo, __half hi)
{
    __half2 v;
    v.x = lo; v.y = hi;
    return *(uint32_t*)&v;
}

__global__ void conv_split_kernel(const float* __restrict__ X,
                                  __half* __restrict__ H,
                                  __half* __restrict__ L, int n4)
{
    int i = blockIdx.x * blockDim.x + threadIdx.x;
    if (i >= n4) return;
    float4 v = *(const float4*)(X + (size_t)i * 4);
    __half h[4], l[4];
    split_f16(v.x, h[0], l[0]);
    split_f16(v.y, h[1], l[1]);
    split_f16(v.z, h[2], l[2]);
    split_f16(v.w, h[3], l[3]);
    *(uint2*)(H + (size_t)i * 4) = *(uint2*)h;
    *(uint2*)(L + (size_t)i * 4) = *(uint2*)l;
}

// transpose + convert: W[K=DIM, N] -> H[N, DIM] fp16
__global__ void wconv_kernel(const float* __restrict__ W,
                             __half* __restrict__ H, int N)
{
    __shared__ float t[32][33];
    const int n0 = blockIdx.x * 32;
    const int k0 = blockIdx.y * 32;
    const int tx = threadIdx.x;
    const int ty = threadIdx.y;
    #pragma unroll
    for (int i = 0; i < 4; i++)
        t[ty + 8 * i][tx] = W[(size_t)(k0 + ty + 8 * i) * N + n0 + tx];
    __syncthreads();
    #pragma unroll
    for (int i = 0; i < 4; i++) {
        float v = t[tx][ty + 8 * i];
        H[(size_t)(n0 + ty + 8 * i) * DIM + k0 + tx] = __float2half_rn(v);
    }
}

// ---------------- HMMA 2-pass split-fp16 GEMM --------------------------------
// C[M,N] = (Ah + Al) * B^T, B rows are [N,K] fp16.
// MODE 0: plain fp32 store to C. MODE 1: fused RoPE + fp16-split QKV epilogue.
#define GK       DIM
#define GCHUNKS  (GK / 32)
#define OPB      8192               // 128 rows x 4 chunks x 16B
#define STAGEB   (3 * OPB)          // 24 KB per stage (Ah, Al, B)
#define NSTAGE   4
#define GEMM_SMEM (NSTAGE * STAGEB) // 96 KB -> 2 CTAs/SM

__device__ __forceinline__ uint32_t chunk_off(int row, int kg) {
    return (uint32_t)(kg * 128 + ((row + 2 * kg) & 127)) * 16u;
}

template<int MODE>
__global__ __launch_bounds__(256, 2) void gemm_hmma(
    const __half* __restrict__ Ah, const __half* __restrict__ Al,
    const __half* __restrict__ B,
    float* __restrict__ C, int N,
    const float* __restrict__ fcos, const float* __restrict__ fsin)
{
    extern __shared__ char smg[];
    const uint32_t sbase = smem_u32(smg);

    const int tid = threadIdx.x;
    const int wid = tid >> 5;
    const int lid = tid & 31;
    const int wm  = wid >> 2;
    const int wn  = wid & 3;
    const int m0  = blockIdx.y * 128;
    const int n0  = blockIdx.x * 128;

    const int lkg = tid & 3;
    const int lr  = tid >> 2;

    auto load_stage = [&](int stage, int kc) {
        const uint32_t sb = sbase + stage * STAGEB;
        const size_t koff = (size_t)kc * 32 + lkg * 8;
        #pragma unroll
        for (int i = 0; i < 2; i++) {
            const int r = lr + i * 64;
            const uint32_t co = chunk_off(r, lkg);
            const size_t ga = (size_t)(m0 + r) * GK + koff;
            const size_t gb = (size_t)(n0 + r) * GK + koff;
            cp_async16(sb + 0 * OPB + co, Ah + ga);
            cp_async16(sb + 1 * OPB + co, Al + ga);
            cp_async16(sb + 2 * OPB + co, B + gb);
        }
    };

    float acc[4][4][4];
    #pragma unroll
    for (int i = 0; i < 4; i++)
        #pragma unroll
        for (int j = 0; j < 4; j++)
            #pragma unroll
            for (int k = 0; k < 4; k++) acc[i][j][k] = 0.f;

    const int sel  = lid >> 3;
    const int lsub = lid & 7;
    const int a_mo = lsub + ((sel & 1) << 3);
    const int a_kg = sel >> 1;
    const int b_no = lsub + ((sel >> 1) << 3);
    const int b_kg = sel & 1;

    load_stage(0, 0); CP_COMMIT();
    load_stage(1, 1); CP_COMMIT();
    load_stage(2, 2); CP_COMMIT();

    for (int kc = 0; kc < GCHUNKS; kc++) {
        const int s = kc & (NSTAGE - 1);
        CP_WAIT(2);
        __syncthreads();

        if (kc + 3 < GCHUNKS) load_stage((kc + 3) & (NSTAGE - 1), kc + 3);
        CP_COMMIT();

        const uint32_t sb = sbase + s * STAGEB;

        #pragma unroll
        for (int ks = 0; ks < 2; ks++) {
            const int kgA = ks * 2 + a_kg;
            const int kgB = ks * 2 + b_kg;

            uint32_t afh[4][4], afl[4][4];
            #pragma unroll
            for (int mt = 0; mt < 4; mt++) {
                const int m = wm * 64 + mt * 16 + a_mo;
                const uint32_t co = chunk_off(m, kgA);
                ldsm4(afh[mt][0], afh[mt][1], afh[mt][2], afh[mt][3],
                      sb + 0 * OPB + co);
                ldsm4(afl[mt][0], afl[mt][1], afl[mt][2], afl[mt][3],
                      sb + 1 * OPB + co);
            }
            uint32_t bf[2][4];
            #pragma unroll
            for (int nt2 = 0; nt2 < 2; nt2++) {
                const int n = wn * 32 + nt2 * 16 + b_no;
                const uint32_t co = chunk_off(n, kgB);
                ldsm4(bf[nt2][0], bf[nt2][1], bf[nt2][2], bf[nt2][3],
                      sb + 2 * OPB + co);
            }
            #pragma unroll
            for (int mt = 0; mt < 4; mt++)
                #pragma unroll
                for (int nt = 0; nt < 4; nt++) {
                    uint32_t b2[2] = { bf[nt >> 1][(nt & 1) << 1],
                                       bf[nt >> 1][((nt & 1) << 1) + 1] };
                    mma_f16(acc[mt][nt], afh[mt], b2);
                    mma_f16(acc[mt][nt], afl[mt], b2);
                }
        }
    }

    const int crow = lid >> 2;
    const int ccol = (lid & 3) * 2;

    if (MODE == 0) {
        #pragma unroll
        for (int mt = 0; mt < 4; mt++) {
            const int r0 = m0 + wm * 64 + mt * 16 + crow;
            #pragma unroll
            for (int nt = 0; nt < 4; nt++) {
                const int c0 = n0 + wn * 32 + nt * 8 + ccol;
                *(float2*)(C + (size_t)r0 * N + c0) =
                    make_float2(acc[mt][nt][0], acc[mt][nt][1]);
                *(float2*)(C + (size_t)(r0 + 8) * N + c0) =
                    make_float2(acc[mt][nt][2], acc[mt][nt][3]);
            }
        }
    } else {
        // fused RoPE + split-fp16 QKV epilogue; route by CTA column block
        const int seg = (n0 < NH * HD) ? 0 : (n0 < NH * HD + NKV * HD ? 1 : 2);
        __half* Hd;
        __half* Ld = nullptr;
        int colbase, rstride;
        if (seg == 0)      { Hd = g_qh; Ld = g_ql; colbase = n0;                rstride = NH * HD;  }
        else if (seg == 1) { Hd = g_kh; Ld = g_kl; colbase = n0 - NH * HD;      rstride = NKV * HD; }
        else               { Hd = g_vh;            colbase = n0 - NH * HD - NKV * HD; rstride = NKV * HD; }

        #pragma unroll
        for (int mt = 0; mt < 4; mt++) {
            const int r0 = m0 + wm * 64 + mt * 16 + crow;
            const int r1 = r0 + 8;
            const int s0 = r0 & (S_ - 1);
            const int s1 = r1 & (S_ - 1);
            #pragma unroll
            for (int nt = 0; nt < 4; nt++) {
                const int c = colbase + wn * 32 + nt * 8 + ccol;
                float v00 = acc[mt][nt][0], v01 = acc[mt][nt][1];
                float v10 = acc[mt][nt][2], v11 = acc[mt][nt][3];
                if (seg < 2) {
                    const int d = (c & (HD - 1)) >> 1;
                    const float c0v = fcos[s0 * (HD / 2) + d];
                    const float s0v = fsin[s0 * (HD / 2) + d];
                    const float c1v = fcos[s1 * (HD / 2) + d];
                    const float s1v = fsin[s1 * (HD / 2) + d];
                    float t00 = v00 * c0v - v01 * s0v;
                    float t01 = v00 * s0v + v01 * c0v;
                    float t10 = v10 * c1v - v11 * s1v;
                    float t11 = v10 * s1v + v11 * c1v;
                    v00 = t00; v01 = t01; v10 = t10; v11 = t11;
                }
                const size_t o0 = (size_t)r0 * rstride + c;
                const size_t o1 = (size_t)r1 * rstride + c;
                __half h0, l0, h1, l1;
                split_f16(v00, h0, l0);
                split_f16(v01, h1, l1);
                *(uint32_t*)(Hd + o0) = pack_f16(h0, h1);
                if (seg < 2) *(uint32_t*)(Ld + o0) = pack_f16(l0, l1);
                split_f16(v10, h0, l0);
                split_f16(v11, h1, l1);
                *(uint32_t*)(Hd + o1) = pack_f16(h0, h1);
                if (seg < 2) *(uint32_t*)(Ld + o1) = pack_f16(l0, l1);
            }
        }
    }
}

// ---------------- HMMA split-fp16 flash attention ---------------------------
// CTA: 128 q rows x one (b, head). S = QK^T 3-pass; O += PV 1-pass (P,V fp16).
#define SQH_OFF 0
#define SQL_OFF 32768
#define STG_OFF 65536
#define STG_SZ  49152              // Kh + Kl + Vh
#define KH_OFF  0
#define KL_OFF  16384
#define VH_OFF  32768
#define ATTN_SMEM (STG_OFF + 2 * STG_SZ)   // 160 KB

__device__ __forceinline__ uint32_t offq(int r, int c) {
    return (uint32_t)(c * 128 + ((r + 2 * c) & 127)) * 16u;
}
__device__ __forceinline__ uint32_t offkv(int r, int c) {
    return (uint32_t)(c * 64 + ((r + 2 * c) & 63)) * 16u;
}

__global__ __launch_bounds__(256, 1) void attn_hmma()
{
    extern __shared__ char sma[];
    const uint32_t sb = smem_u32(sma);

    const int tid = threadIdx.x;
    const int wid = tid >> 5;
    const int lid = tid & 31;
    const int bx  = gridDim.x - 1 - blockIdx.x;   // LPT: longest CTAs first
    const int h   = blockIdx.y;
    const int bz  = blockIdx.z;
    const int g   = h >> 2;
    const int qm0 = bx * 128;
    const int tb  = bz * S_;
    const int ntiles = 2 * (bx + 1);

    const int sel  = lid >> 3;
    const int lsub = lid & 7;
    const int a_r  = wid * 16 + lsub + ((sel & 1) << 3);
    const int a_co = sel >> 1;
    const int b_r  = lsub + ((sel >> 1) << 3);
    const int b_co = sel & 1;
    const int v_r  = lsub + ((sel & 1) << 3);
    const int v_co = sel >> 1;

    const int lc = tid & 15;
    const int lr = tid >> 4;

    // Q (once): 128 rows x 16 chunks x {h,l}
    {
        #pragma unroll
        for (int i = 0; i < 8; i++) {
            const int r = lr + 16 * i;
            const size_t go = ((size_t)(tb + qm0 + r) * NH + h) * HD + lc * 8;
            const uint32_t o = offq(r, lc);
            cp_async16(sb + SQH_OFF + o, g_qh + go);
            cp_async16(sb + SQL_OFF + o, g_ql + go);
        }
    }
    auto load_kv = [&](int stage, int t) {
        const uint32_t st = sb + STG_OFF + stage * STG_SZ;
        const int j0 = t * 64;
        #pragma unroll
        for (int i = 0; i < 4; i++) {
            const int r = lr + 16 * i;
            const size_t go = ((size_t)(tb + j0 + r) * NKV + g) * HD + lc * 8;
            const uint32_t o = offkv(r, lc);
            cp_async16(st + KH_OFF + o, g_kh + go);
            cp_async16(st + KL_OFF + o, g_kl + go);
            cp_async16(st + VH_OFF + o, g_vh + go);
        }
    };

    load_kv(0, 0); CP_COMMIT();
    if (ntiles > 1) { load_kv(1, 1); }
    CP_COMMIT();

    float o[16][4];
    #pragma unroll
    for (int i = 0; i < 16; i++)
        #pragma unroll
        for (int j = 0; j < 4; j++) o[i][j] = 0.f;
    float m_lo = -1e30f, m_hi = -1e30f;
    float l_lo = 0.f, l_hi = 0.f;
    const float scale = 0.08838834764831843f;
    const int row_lo = qm0 + wid * 16 + (lid >> 2);
    const int col_l  = (lid & 3) * 2;

    for (int t = 0; t < ntiles; t++) {
        if (t + 1 < ntiles) { CP_WAIT(1); } else { CP_WAIT(0); }
        __syncthreads();

        const uint32_t stb = sb + STG_OFF + (t & 1) * STG_SZ;
        const bool masked = (t >= 2 * bx);
        const int j0 = t * 64;

        // ---- S = Q K^T (3-pass fp16) ----
        float sacc[8][4];
        #pragma unroll
        for (int i = 0; i < 8; i++)
            #pragma unroll
            for (int j = 0; j < 4; j++) sacc[i][j] = 0.f;

        #pragma unroll
        for (int kt = 0; kt < 8; kt++) {
            uint32_t qh[4], ql[4];
            const uint32_t qo = offq(a_r, 2 * kt + a_co);
            ldsm4(qh[0], qh[1], qh[2], qh[3], sb + SQH_OFF + qo);
            ldsm4(ql[0], ql[1], ql[2], ql[3], sb + SQL_OFF + qo);
            uint32_t kh[4][4], kl[4][4];
            #pragma unroll
            for (int np = 0; np < 4; np++) {
                const uint32_t ko = offkv(np * 16 + b_r, 2 * kt + b_co);
                ldsm4(kh[np][0], kh[np][1], kh[np][2], kh[np][3],
                      stb + KH_OFF + ko);
                ldsm4(kl[np][0], kl[np][1], kl[np][2], kl[np][3],
                      stb + KL_OFF + ko);
            }
            #pragma unroll
            for (int nt = 0; nt < 8; nt++) {
                uint32_t bh[2] = { kh[nt >> 1][(nt & 1) << 1],
                                   kh[nt >> 1][((nt & 1) << 1) + 1] };
                uint32_t bl[2] = { kl[nt >> 1][(nt & 1) << 1],
                                   kl[nt >> 1][((nt & 1) << 1) + 1] };
                mma_f16(sacc[nt], qh, bh);
                mma_f16(sacc[nt], ql, bh);
                mma_f16(sacc[nt], qh, bl);
            }
        }

        // ---- scale + causal mask ----
        if (masked) {
            #pragma unroll
            for (int nt = 0; nt < 8; nt++) {
                const int c0 = j0 + nt * 8 + col_l;
                sacc[nt][0] = (c0     <= row_lo)     ? sacc[nt][0] * scale : -1e30f;
                sacc[nt][1] = (c0 + 1 <= row_lo)     ? sacc[nt][1] * scale : -1e30f;
                sacc[nt][2] = (c0     <= row_lo + 8) ? sacc[nt][2] * scale : -1e30f;
                sacc[nt][3] = (c0 + 1 <= row_lo + 8) ? sacc[nt][3] * scale : -1e30f;
            }
        } else {
            #pragma unroll
            for (int nt = 0; nt < 8; nt++)
                #pragma unroll
                for (int e = 0; e < 4; e++) sacc[nt][e] *= scale;
        }

        // ---- online softmax ----
        float mx_lo = -1e30f, mx_hi = -1e30f;
        #pragma unroll
        for (int nt = 0; nt < 8; nt++) {
            mx_lo = fmaxf(mx_lo, fmaxf(sacc[nt][0], sacc[nt][1]));
            mx_hi = fmaxf(mx_hi, fmaxf(sacc[nt][2], sacc[nt][3]));
        }
        #pragma unroll
        for (int off = 1; off < 4; off <<= 1) {
            mx_lo = fmaxf(mx_lo, __shfl_xor_sync(0xffffffffu, mx_lo, off));
            mx_hi = fmaxf(mx_hi, __shfl_xor_sync(0xffffffffu, mx_hi, off));
        }
        const float mn_lo = fmaxf(m_lo, mx_lo);
        const float mn_hi = fmaxf(m_hi, mx_hi);
        const float al_lo = __expf(m_lo - mn_lo);
        const float al_hi = __expf(m_hi - mn_hi);
        m_lo = mn_lo; m_hi = mn_hi;

        float sum_lo = 0.f, sum_hi = 0.f;
        uint32_t aph[4][4];
        #pragma unroll
        for (int kt2 = 0; kt2 < 4; kt2++) {
            float p[2][4];
            #pragma unroll
            for (int half = 0; half < 2; half++) {
                const int nt = 2 * kt2 + half;
                p[half][0] = __expf(sacc[nt][0] - mn_lo);
                p[half][1] = __expf(sacc[nt][1] - mn_lo);
                p[half][2] = __expf(sacc[nt][2] - mn_hi);
                p[half][3] = __expf(sacc[nt][3] - mn_hi);
                sum_lo += p[half][0] + p[half][1];
                sum_hi += p[half][2] + p[half][3];
            }
            #pragma unroll
            for (int half = 0; half < 2; half++) {
                aph[kt2][0 + 2 * half] = pack_f16(__float2half_rn(p[half][0]),
                                                  __float2half_rn(p[half][1]));
                aph[kt2][1 + 2 * half] = pack_f16(__float2half_rn(p[half][2]),
                                                  __float2half_rn(p[half][3]));
            }
        }
        #pragma unroll
        for (int off = 1; off < 4; off <<= 1) {
            sum_lo += __shfl_xor_sync(0xffffffffu, sum_lo, off);
            sum_hi += __shfl_xor_sync(0xffffffffu, sum_hi, off);
        }
        l_lo = l_lo * al_lo + sum_lo;
        l_hi = l_hi * al_hi + sum_hi;
        #pragma unroll
        for (int dt = 0; dt < 16; dt++) {
            o[dt][0] *= al_lo; o[dt][1] *= al_lo;
            o[dt][2] *= al_hi; o[dt][3] *= al_hi;
        }

        // ---- O += P V (1-pass fp16) ----
        #pragma unroll
        for (int kt2 = 0; kt2 < 4; kt2++) {
            #pragma unroll
            for (int dp = 0; dp < 8; dp++) {
                uint32_t vh[4];
                const uint32_t vo = offkv(kt2 * 16 + v_r, 2 * dp + v_co);
                ldsm4t(vh[0], vh[1], vh[2], vh[3], stb + VH_OFF + vo);
                #pragma unroll
                for (int d2 = 0; d2 < 2; d2++) {
                    const int dt = 2 * dp + d2;
                    uint32_t bh[2] = { vh[d2 * 2], vh[d2 * 2 + 1] };
                    mma_f16(o[dt], aph[kt2], bh);
                }
            }
        }

        __syncthreads();
        if (t + 2 < ntiles) { load_kv(t & 1, t + 2); }
        CP_COMMIT();
    }

    // ---- epilogue: normalize + split-fp16 store ----
    const float inv_lo = 1.f / l_lo;
    const float inv_hi = 1.f / l_hi;
    const size_t ro_lo = ((size_t)(tb + row_lo) * NH + h) * HD;
    const size_t ro_hi = ro_lo + (size_t)8 * NH * HD;
    #pragma unroll
    for (int dt = 0; dt < 16; dt++) {
        const int c = dt * 8 + col_l;
        float f0 = o[dt][0] * inv_lo, f1 = o[dt][1] * inv_lo;
        float f2 = o[dt][2] * inv_hi, f3 = o[dt][3] * inv_hi;
        __half h0, l0, h1, l1, h2, l2, h3, l3;
        split_f16(f0, h0, l0);
        split_f16(f1, h1, l1);
        split_f16(f2, h2, l2);
        split_f16(f3, h3, l3);
        *(uint32_t*)(g_oh + ro_lo + c) = pack_f16(h0, h1);
        *(uint32_t*)(g_ol + ro_lo + c) = pack_f16(l0, l1);
        *(uint32_t*)(g_oh + ro_hi + c) = pack_f16(h2, h3);
        *(uint32_t*)(g_ol + ro_hi + c) = pack_f16(l2, l3);
    }
}

// ---------------- launch ----------------------------------------------------
extern "C" void kernel_launch(void* const* d_in, const int* in_sizes, int n_in,
                              void* d_out, int out_size)
{
    const float* x    = (const float*)d_in[0];
    const float* fcos = (const float*)d_in[2];
    const float* fsin = (const float*)d_in[3];
    const float* wq   = (const float*)d_in[6];
    const float* wk   = (const float*)d_in[7];
    const float* wv   = (const float*)d_in[8];
    const float* wo   = (const float*)d_in[9];
    float* out        = (float*)d_out;

    __half *xh, *xl, *oh, *ol, *wqkv, *wot;
    cudaGetSymbolAddress((void**)&xh, g_xh);
    cudaGetSymbolAddress((void**)&xl, g_xl);
    cudaGetSymbolAddress((void**)&oh, g_oh);
    cudaGetSymbolAddress((void**)&ol, g_ol);
    cudaGetSymbolAddress((void**)&wqkv, g_wqkv);
    cudaGetSymbolAddress((void**)&wot, g_wot);

    cudaFuncSetAttribute(gemm_hmma<0>, cudaFuncAttributeMaxDynamicSharedMemorySize, GEMM_SMEM);
    cudaFuncSetAttribute(gemm_hmma<1>, cudaFuncAttributeMaxDynamicSharedMemorySize, GEMM_SMEM);
    cudaFuncSetAttribute(attn_hmma, cudaFuncAttributeMaxDynamicSharedMemorySize, ATTN_SMEM);

    // launches 1-4: conversions (x split; wq/wk/wv transposed into one array)
    conv_split_kernel<<<(T_ * DIM / 4 + 255) / 256, 256>>>(x, xh, xl, T_ * DIM / 4);
    wconv_kernel<<<dim3(DIM / 32, DIM / 32), dim3(32, 8)>>>(wq, wqkv, DIM);
    wconv_kernel<<<dim3((NKV * HD) / 32, DIM / 32), dim3(32, 8)>>>(wk, wqkv + (size_t)(NH * HD) * DIM, NKV * HD);
    wconv_kernel<<<dim3((NKV * HD) / 32, DIM / 32), dim3(32, 8)>>>(wv, wqkv + (size_t)(NH * HD + NKV * HD) * DIM, NKV * HD);

    // launch 5: fused QKV projection + RoPE + fp16 split  (ncu -s 5 profiles this)
    gemm_hmma<1><<<dim3(NQKV / 128, T_ / 128), 256, GEMM_SMEM>>>(
        xh, xl, wqkv, out, NQKV, fcos, fsin);

    // launch 6: attention
    attn_hmma<<<dim3(S_ / 128, NH, B_), 256, ATTN_SMEM>>>();

    // launches 7-8: wo conversion + output projection
    wconv_kernel<<<dim3(DIM / 32, DIM / 32), dim3(32, 8)>>>(wo, wot, DIM);
    gemm_hmma<0><<<dim3(DIM / 128, T_ / 128), 256, GEMM_SMEM>>>(
        oh, ol, wot, out, DIM, fcos, fsin);
}

// round 8
// speedup vs baseline: 3.2166x; 1.0158x over previous
#include <cuda_runtime.h>
#include <cuda_fp16.h>
#include <cstdint>
#include <math.h>

#define DIM 4096
#define NH  32
#define NKV 8
#define HD  128
#define B_  2
#define S_  2048
#define T_  (B_*S_)          // 4096 tokens
#define NREP 4
#define NQKV 6144            // NH*HD + 2*NKV*HD

// ---------------- scratch (device globals; no cudaMalloc allowed) ----------
__device__ __half g_xh[(size_t)T_ * DIM];
__device__ __half g_xl[(size_t)T_ * DIM];
__device__ __half g_oh[(size_t)T_ * DIM];
__device__ __half g_ol[(size_t)T_ * DIM];
__device__ __half g_qh[(size_t)T_ * NH * HD];
__device__ __half g_ql[(size_t)T_ * NH * HD];
__device__ __half g_kh[(size_t)T_ * NKV * HD];
__device__ __half g_kl[(size_t)T_ * NKV * HD];
__device__ __half g_vh[(size_t)T_ * NKV * HD];
__device__ __half g_wqkv[(size_t)NQKV * DIM];   // [wq | wk | wv] transposed
__device__ __half g_wot[(size_t)DIM * DIM];

// ---------------- low-level helpers (sm_103 base-target safe) --------------
__device__ __forceinline__ uint32_t smem_u32(const void* p) {
    uint32_t a;
    asm("{ .reg .u64 t; cvta.to.shared.u64 t, %1; cvt.u32.u64 %0, t; }"
        : "=r"(a) : "l"(p));
    return a;
}
__device__ __forceinline__ void cp_async16(uint32_t dst, const void* src) {
    asm volatile("cp.async.cg.shared.global [%0], [%1], 16;"
                 :: "r"(dst), "l"(src));
}
#define CP_COMMIT() asm volatile("cp.async.commit_group;" ::: "memory")
#define CP_WAIT(n)  asm volatile("cp.async.wait_group %0;" :: "n"(n) : "memory")

__device__ __forceinline__ void ldsm4(uint32_t& r0, uint32_t& r1,
                                      uint32_t& r2, uint32_t& r3, uint32_t a) {
    asm volatile("ldmatrix.sync.aligned.m8n8.x4.shared.b16 {%0,%1,%2,%3}, [%4];"
                 : "=r"(r0), "=r"(r1), "=r"(r2), "=r"(r3) : "r"(a));
}
__device__ __forceinline__ void ldsm4t(uint32_t& r0, uint32_t& r1,
                                       uint32_t& r2, uint32_t& r3, uint32_t a) {
    asm volatile("ldmatrix.sync.aligned.m8n8.x4.trans.shared.b16 {%0,%1,%2,%3}, [%4];"
                 : "=r"(r0), "=r"(r1), "=r"(r2), "=r"(r3) : "r"(a));
}
__device__ __forceinline__ void mma_f16(float* c, const uint32_t* a,
                                        const uint32_t* b) {
    asm volatile(
        "mma.sync.aligned.m16n8k16.row.col.f32.f16.f16.f32 "
        "{%0,%1,%2,%3}, {%4,%5,%6,%7}, {%8,%9}, {%0,%1,%2,%3};"
        : "+f"(c[0]), "+f"(c[1]), "+f"(c[2]), "+f"(c[3])
        : "r"(a[0]), "r"(a[1]), "r"(a[2]), "r"(a[3]), "r"(b[0]), "r"(b[1]));
}

// ---------------- split-fp16 conversion -------------------------------------
__device__ __forceinline__ void split_f16(float x, __half& h, __half& l)
{
    h = __float2half_rn(x);
    l = __float2half_rn(x - __half2float(h));
}
__device__ __forceinline__ uint32_t pack_f16(__half lo, __half hi)
{
    __half2 v;
    v.x = lo; v.y = hi;
    return *(uint32_t*)&v;
}

__global__ void conv_split_kernel(const float* __restrict__ X,
                                  __half* __restrict__ H,
                                  __half* __restrict__ L, int n4)
{
    int i = blockIdx.x * blockDim.x + threadIdx.x;
    if (i >= n4) return;
    float4 v = *(const float4*)(X + (size_t)i * 4);
    __half h[4], l[4];
    split_f16(v.x, h[0], l[0]);
    split_f16(v.y, h[1], l[1]);
    split_f16(v.z, h[2], l[2]);
    split_f16(v.w, h[3], l[3]);
    *(uint2*)(H + (size_t)i * 4) = *(uint2*)h;
    *(uint2*)(L + (size_t)i * 4) = *(uint2*)l;
}

// transpose + convert: W[K=DIM, N] -> H[N, DIM] fp16
__global__ void wconv_kernel(const float* __restrict__ W,
                             __half* __restrict__ H, int N)
{
    __shared__ float t[32][33];
    const int n0 = blockIdx.x * 32;
    const int k0 = blockIdx.y * 32;
    const int tx = threadIdx.x;
    const int ty = threadIdx.y;
    #pragma unroll
    for (int i = 0; i < 4; i++)
        t[ty + 8 * i][tx] = W[(size_t)(k0 + ty + 8 * i) * N + n0 + tx];
    __syncthreads();
    #pragma unroll
    for (int i = 0; i < 4; i++) {
        float v = t[tx][ty + 8 * i];
        H[(size_t)(n0 + ty + 8 * i) * DIM + k0 + tx] = __float2half_rn(v);
    }
}

// ---------------- HMMA 2-pass split-fp16 GEMM (128x256 tile) ----------------
// C[M,N] = (Ah + Al) * B^T, B rows are [N,K] fp16. 512 threads, 16 warps 4x4.
// MODE 0: plain fp32 store. MODE 1: fused RoPE + fp16-split QKV epilogue.
#define GK       DIM
#define GCHUNKS  (GK / 32)
#define A_H_OFF  0
#define A_L_OFF  8192
#define B_OFF    16384
#define STAGEB   32768              // Ah(8K) + Al(8K) + B(16K)
#define NSTAGE   4
#define GEMM_SMEM (NSTAGE * STAGEB) // 128 KB

__device__ __forceinline__ uint32_t chunk_offA(int row, int kg) {
    return (uint32_t)(kg * 128 + ((row + 2 * kg) & 127)) * 16u;
}
__device__ __forceinline__ uint32_t chunk_offB(int row, int kg) {
    return (uint32_t)(kg * 256 + ((row + 2 * kg) & 255)) * 16u;
}

template<int MODE>
__global__ __launch_bounds__(512, 1) void gemm_hmma(
    const __half* __restrict__ Ah, const __half* __restrict__ Al,
    const __half* __restrict__ B,
    float* __restrict__ C, int N,
    const float* __restrict__ fcos, const float* __restrict__ fsin)
{
    extern __shared__ char smg[];
    const uint32_t sbase = smem_u32(smg);

    const int tid = threadIdx.x;
    const int wid = tid >> 5;
    const int lid = tid & 31;
    const int wm  = wid >> 2;      // 0..3 (32 rows each)
    const int wn  = wid & 3;       // 0..3 (64 cols each)
    const int m0  = blockIdx.y * 128;
    const int n0  = blockIdx.x * 256;

    const int lkg = tid & 3;
    const int lr  = tid >> 2;      // 0..127

    auto load_stage = [&](int stage, int kc) {
        const uint32_t sb = sbase + stage * STAGEB;
        const size_t koff = (size_t)kc * 32 + lkg * 8;
        const uint32_t coA = chunk_offA(lr, lkg);
        const size_t ga = (size_t)(m0 + lr) * GK + koff;
        cp_async16(sb + A_H_OFF + coA, Ah + ga);
        cp_async16(sb + A_L_OFF + coA, Al + ga);
        #pragma unroll
        for (int i = 0; i < 2; i++) {
            const int r = lr + i * 128;
            const uint32_t coB = chunk_offB(r, lkg);
            const size_t gb = (size_t)(n0 + r) * GK + koff;
            cp_async16(sb + B_OFF + coB, B + gb);
        }
    };

    float acc[2][8][4];
    #pragma unroll
    for (int i = 0; i < 2; i++)
        #pragma unroll
        for (int j = 0; j < 8; j++)
            #pragma unroll
            for (int k = 0; k < 4; k++) acc[i][j][k] = 0.f;

    const int sel  = lid >> 3;
    const int lsub = lid & 7;
    const int a_mo = lsub + ((sel & 1) << 3);
    const int a_kg = sel >> 1;
    const int b_no = lsub + ((sel >> 1) << 3);
    const int b_kg = sel & 1;

    load_stage(0, 0); CP_COMMIT();
    load_stage(1, 1); CP_COMMIT();
    load_stage(2, 2); CP_COMMIT();

    for (int kc = 0; kc < GCHUNKS; kc++) {
        const int s = kc & (NSTAGE - 1);
        CP_WAIT(2);
        __syncthreads();

        if (kc + 3 < GCHUNKS) load_stage((kc + 3) & (NSTAGE - 1), kc + 3);
        CP_COMMIT();

        const uint32_t sb = sbase + s * STAGEB;

        #pragma unroll
        for (int ks = 0; ks < 2; ks++) {
            const int kgA = ks * 2 + a_kg;
            const int kgB = ks * 2 + b_kg;

            uint32_t afh[2][4], afl[2][4];
            #pragma unroll
            for (int mt = 0; mt < 2; mt++) {
                const int m = wm * 32 + mt * 16 + a_mo;
                const uint32_t co = chunk_offA(m, kgA);
                ldsm4(afh[mt][0], afh[mt][1], afh[mt][2], afh[mt][3],
                      sb + A_H_OFF + co);
                ldsm4(afl[mt][0], afl[mt][1], afl[mt][2], afl[mt][3],
                      sb + A_L_OFF + co);
            }
            uint32_t bf[4][4];
            #pragma unroll
            for (int nt2 = 0; nt2 < 4; nt2++) {
                const int n = wn * 64 + nt2 * 16 + b_no;
                const uint32_t co = chunk_offB(n, kgB);
                ldsm4(bf[nt2][0], bf[nt2][1], bf[nt2][2], bf[nt2][3],
                      sb + B_OFF + co);
            }
            #pragma unroll
            for (int mt = 0; mt < 2; mt++)
                #pragma unroll
                for (int nt = 0; nt < 8; nt++) {
                    uint32_t b2[2] = { bf[nt >> 1][(nt & 1) << 1],
                                       bf[nt >> 1][((nt & 1) << 1) + 1] };
                    mma_f16(acc[mt][nt], afh[mt], b2);
                    mma_f16(acc[mt][nt], afl[mt], b2);
                }
        }
    }

    const int crow = lid >> 2;
    const int ccol = (lid & 3) * 2;

    if (MODE == 0) {
        #pragma unroll
        for (int mt = 0; mt < 2; mt++) {
            const int r0 = m0 + wm * 32 + mt * 16 + crow;
            #pragma unroll
            for (int nt = 0; nt < 8; nt++) {
                const int c0 = n0 + wn * 64 + nt * 8 + ccol;
                *(float2*)(C + (size_t)r0 * N + c0) =
                    make_float2(acc[mt][nt][0], acc[mt][nt][1]);
                *(float2*)(C + (size_t)(r0 + 8) * N + c0) =
                    make_float2(acc[mt][nt][2], acc[mt][nt][3]);
            }
        }
    } else {
        // fused RoPE + split-fp16 QKV epilogue; route by CTA column block
        const int seg = (n0 < NH * HD) ? 0 : (n0 < NH * HD + NKV * HD ? 1 : 2);
        __half* Hd;
        __half* Ld = nullptr;
        int colbase, rstride;
        if (seg == 0)      { Hd = g_qh; Ld = g_ql; colbase = n0;                rstride = NH * HD;  }
        else if (seg == 1) { Hd = g_kh; Ld = g_kl; colbase = n0 - NH * HD;      rstride = NKV * HD; }
        else               { Hd = g_vh;            colbase = n0 - NH * HD - NKV * HD; rstride = NKV * HD; }

        #pragma unroll
        for (int mt = 0; mt < 2; mt++) {
            const int r0 = m0 + wm * 32 + mt * 16 + crow;
            const int r1 = r0 + 8;
            const int s0 = r0 & (S_ - 1);
            const int s1 = r1 & (S_ - 1);
            #pragma unroll
            for (int nt = 0; nt < 8; nt++) {
                const int c = colbase + wn * 64 + nt * 8 + ccol;
                float v00 = acc[mt][nt][0], v01 = acc[mt][nt][1];
                float v10 = acc[mt][nt][2], v11 = acc[mt][nt][3];
                if (seg < 2) {
                    const int d = (c & (HD - 1)) >> 1;
                    const float c0v = fcos[s0 * (HD / 2) + d];
                    const float s0v = fsin[s0 * (HD / 2) + d];
                    const float c1v = fcos[s1 * (HD / 2) + d];
                    const float s1v = fsin[s1 * (HD / 2) + d];
                    float t00 = v00 * c0v - v01 * s0v;
                    float t01 = v00 * s0v + v01 * c0v;
                    float t10 = v10 * c1v - v11 * s1v;
                    float t11 = v10 * s1v + v11 * c1v;
                    v00 = t00; v01 = t01; v10 = t10; v11 = t11;
                }
                const size_t o0 = (size_t)r0 * rstride + c;
                const size_t o1 = (size_t)r1 * rstride + c;
                __half h0, l0, h1, l1;
                split_f16(v00, h0, l0);
                split_f16(v01, h1, l1);
                *(uint32_t*)(Hd + o0) = pack_f16(h0, h1);
                if (seg < 2) *(uint32_t*)(Ld + o0) = pack_f16(l0, l1);
                split_f16(v10, h0, l0);
                split_f16(v11, h1, l1);
                *(uint32_t*)(Hd + o1) = pack_f16(h0, h1);
                if (seg < 2) *(uint32_t*)(Ld + o1) = pack_f16(l0, l1);
            }
        }
    }
}

// ---------------- HMMA split-fp16 flash attention ---------------------------
// CTA: 128 q rows x one (b, head). S = QK^T 3-pass; O += PV 1-pass (P,V fp16).
#define SQH_OFF 0
#define SQL_OFF 32768
#define STG_OFF 65536
#define STG_SZ  49152              // Kh + Kl + Vh
#define KH_OFF  0
#define KL_OFF  16384
#define VH_OFF  32768
#define ATTN_SMEM (STG_OFF + 2 * STG_SZ)   // 160 KB

__device__ __forceinline__ uint32_t offq(int r, int c) {
    return (uint32_t)(c * 128 + ((r + 2 * c) & 127)) * 16u;
}
__device__ __forceinline__ uint32_t offkv(int r, int c) {
    return (uint32_t)(c * 64 + ((r + 2 * c) & 63)) * 16u;
}

__global__ __launch_bounds__(256, 1) void attn_hmma()
{
    extern __shared__ char sma[];
    const uint32_t sb = smem_u32(sma);

    const int tid = threadIdx.x;
    const int wid = tid >> 5;
    const int lid = tid & 31;
    const int bx  = gridDim.x - 1 - blockIdx.x;   // LPT: longest CTAs first
    const int h   = blockIdx.y;
    const int bz  = blockIdx.z;
    const int g   = h >> 2;
    const int qm0 = bx * 128;
    const int tb  = bz * S_;
    const int ntiles = 2 * (bx + 1);

    const int sel  = lid >> 3;
    const int lsub = lid & 7;
    const int a_r  = wid * 16 + lsub + ((sel & 1) << 3);
    const int a_co = sel >> 1;
    const int b_r  = lsub + ((sel >> 1) << 3);
    const int b_co = sel & 1;
    const int v_r  = lsub + ((sel & 1) << 3);
    const int v_co = sel >> 1;

    const int lc = tid & 15;
    const int lr = tid >> 4;

    // Q (once): 128 rows x 16 chunks x {h,l}
    {
        #pragma unroll
        for (int i = 0; i < 8; i++) {
            const int r = lr + 16 * i;
            const size_t go = ((size_t)(tb + qm0 + r) * NH + h) * HD + lc * 8;
            const uint32_t o = offq(r, lc);
            cp_async16(sb + SQH_OFF + o, g_qh + go);
            cp_async16(sb + SQL_OFF + o, g_ql + go);
        }
    }
    auto load_kv = [&](int stage, int t) {
        const uint32_t st = sb + STG_OFF + stage * STG_SZ;
        const int j0 = t * 64;
        #pragma unroll
        for (int i = 0; i < 4; i++) {
            const int r = lr + 16 * i;
            const size_t go = ((size_t)(tb + j0 + r) * NKV + g) * HD + lc * 8;
            const uint32_t o = offkv(r, lc);
            cp_async16(st + KH_OFF + o, g_kh + go);
            cp_async16(st + KL_OFF + o, g_kl + go);
            cp_async16(st + VH_OFF + o, g_vh + go);
        }
    };

    load_kv(0, 0); CP_COMMIT();
    if (ntiles > 1) { load_kv(1, 1); }
    CP_COMMIT();

    float o[16][4];
    #pragma unroll
    for (int i = 0; i < 16; i++)
        #pragma unroll
        for (int j = 0; j < 4; j++) o[i][j] = 0.f;
    float m_lo = -1e30f, m_hi = -1e30f;
    float l_lo = 0.f, l_hi = 0.f;
    const float scale = 0.08838834764831843f;
    const int row_lo = qm0 + wid * 16 + (lid >> 2);
    const int col_l  = (lid & 3) * 2;

    for (int t = 0; t < ntiles; t++) {
        if (t + 1 < ntiles) { CP_WAIT(1); } else { CP_WAIT(0); }
        __syncthreads();

        const uint32_t stb = sb + STG_OFF + (t & 1) * STG_SZ;
        const bool masked = (t >= 2 * bx);
        const int j0 = t * 64;

        // ---- S = Q K^T (3-pass fp16) ----
        float sacc[8][4];
        #pragma unroll
        for (int i = 0; i < 8; i++)
            #pragma unroll
            for (int j = 0; j < 4; j++) sacc[i][j] = 0.f;

        #pragma unroll
        for (int kt = 0; kt < 8; kt++) {
            uint32_t qh[4], ql[4];
            const uint32_t qo = offq(a_r, 2 * kt + a_co);
            ldsm4(qh[0], qh[1], qh[2], qh[3], sb + SQH_OFF + qo);
            ldsm4(ql[0], ql[1], ql[2], ql[3], sb + SQL_OFF + qo);
            uint32_t kh[4][4], kl[4][4];
            #pragma unroll
            for (int np = 0; np < 4; np++) {
                const uint32_t ko = offkv(np * 16 + b_r, 2 * kt + b_co);
                ldsm4(kh[np][0], kh[np][1], kh[np][2], kh[np][3],
                      stb + KH_OFF + ko);
                ldsm4(kl[np][0], kl[np][1], kl[np][2], kl[np][3],
                      stb + KL_OFF + ko);
            }
            #pragma unroll
            for (int nt = 0; nt < 8; nt++) {
                uint32_t bh[2] = { kh[nt >> 1][(nt & 1) << 1],
                                   kh[nt >> 1][((nt & 1) << 1) + 1] };
                uint32_t bl[2] = { kl[nt >> 1][(nt & 1) << 1],
                                   kl[nt >> 1][((nt & 1) << 1) + 1] };
                mma_f16(sacc[nt], qh, bh);
                mma_f16(sacc[nt], ql, bh);
                mma_f16(sacc[nt], qh, bl);
            }
        }

        // ---- scale + causal mask ----
        if (masked) {
            #pragma unroll
            for (int nt = 0; nt < 8; nt++) {
                const int c0 = j0 + nt * 8 + col_l;
                sacc[nt][0] = (c0     <= row_lo)     ? sacc[nt][0] * scale : -1e30f;
                sacc[nt][1] = (c0 + 1 <= row_lo)     ? sacc[nt][1] * scale : -1e30f;
                sacc[nt][2] = (c0     <= row_lo + 8) ? sacc[nt][2] * scale : -1e30f;
                sacc[nt][3] = (c0 + 1 <= row_lo + 8) ? sacc[nt][3] * scale : -1e30f;
            }
        } else {
            #pragma unroll
            for (int nt = 0; nt < 8; nt++)
                #pragma unroll
                for (int e = 0; e < 4; e++) sacc[nt][e] *= scale;
        }

        // ---- online softmax ----
        float mx_lo = -1e30f, mx_hi = -1e30f;
        #pragma unroll
        for (int nt = 0; nt < 8; nt++) {
            mx_lo = fmaxf(mx_lo, fmaxf(sacc[nt][0], sacc[nt][1]));
            mx_hi = fmaxf(mx_hi, fmaxf(sacc[nt][2], sacc[nt][3]));
        }
        #pragma unroll
        for (int off = 1; off < 4; off <<= 1) {
            mx_lo = fmaxf(mx_lo, __shfl_xor_sync(0xffffffffu, mx_lo, off));
            mx_hi = fmaxf(mx_hi, __shfl_xor_sync(0xffffffffu, mx_hi, off));
        }
        const float mn_lo = fmaxf(m_lo, mx_lo);
        const float mn_hi = fmaxf(m_hi, mx_hi);
        const float al_lo = __expf(m_lo - mn_lo);
        const float al_hi = __expf(m_hi - mn_hi);
        m_lo = mn_lo; m_hi = mn_hi;

        float sum_lo = 0.f, sum_hi = 0.f;
        uint32_t aph[4][4];
        #pragma unroll
        for (int kt2 = 0; kt2 < 4; kt2++) {
            float p[2][4];
            #pragma unroll
            for (int half = 0; half < 2; half++) {
                const int nt = 2 * kt2 + half;
                p[half][0] = __expf(sacc[nt][0] - mn_lo);
                p[half][1] = __expf(sacc[nt][1] - mn_lo);
                p[half][2] = __expf(sacc[nt][2] - mn_hi);
                p[half][3] = __expf(sacc[nt][3] - mn_hi);
                sum_lo += p[half][0] + p[half][1];
                sum_hi += p[half][2] + p[half][3];
            }
            #pragma unroll
            for (int half = 0; half < 2; half++) {
                aph[kt2][0 + 2 * half] = pack_f16(__float2half_rn(p[half][0]),
                                                  __float2half_rn(p[half][1]));
                aph[kt2][1 + 2 * half] = pack_f16(__float2half_rn(p[half][2]),
                                                  __float2half_rn(p[half][3]));
            }
        }
        #pragma unroll
        for (int off = 1; off < 4; off <<= 1) {
            sum_lo += __shfl_xor_sync(0xffffffffu, sum_lo, off);
            sum_hi += __shfl_xor_sync(0xffffffffu, sum_hi, off);
        }
        l_lo = l_lo * al_lo + sum_lo;
        l_hi = l_hi * al_hi + sum_hi;
        #pragma unroll
        for (int dt = 0; dt < 16; dt++) {
            o[dt][0] *= al_lo; o[dt][1] *= al_lo;
            o[dt][2] *= al_hi; o[dt][3] *= al_hi;
        }

        // ---- O += P V (1-pass fp16) ----
        #pragma unroll
        for (int kt2 = 0; kt2 < 4; kt2++) {
            #pragma unroll
            for (int dp = 0; dp < 8; dp++) {
                uint32_t vh[4];
                const uint32_t vo = offkv(kt2 * 16 + v_r, 2 * dp + v_co);
                ldsm4t(vh[0], vh[1], vh[2], vh[3], stb + VH_OFF + vo);
                #pragma unroll
                for (int d2 = 0; d2 < 2; d2++) {
                    const int dt = 2 * dp + d2;
                    uint32_t bh[2] = { vh[d2 * 2], vh[d2 * 2 + 1] };
                    mma_f16(o[dt], aph[kt2], bh);
                }
            }
        }

        __syncthreads();
        if (t + 2 < ntiles) { load_kv(t & 1, t + 2); }
        CP_COMMIT();
    }

    // ---- epilogue: normalize + split-fp16 store ----
    const float inv_lo = 1.f / l_lo;
    const float inv_hi = 1.f / l_hi;
    const size_t ro_lo = ((size_t)(tb + row_lo) * NH + h) * HD;
    const size_t ro_hi = ro_lo + (size_t)8 * NH * HD;
    #pragma unroll
    for (int dt = 0; dt < 16; dt++) {
        const int c = dt * 8 + col_l;
        float f0 = o[dt][0] * inv_lo, f1 = o[dt][1] * inv_lo;
        float f2 = o[dt][2] * inv_hi, f3 = o[dt][3] * inv_hi;
        __half h0, l0, h1, l1, h2, l2, h3, l3;
        split_f16(f0, h0, l0);
        split_f16(f1, h1, l1);
        split_f16(f2, h2, l2);
        split_f16(f3, h3, l3);
        *(uint32_t*)(g_oh + ro_lo + c) = pack_f16(h0, h1);
        *(uint32_t*)(g_ol + ro_lo + c) = pack_f16(l0, l1);
        *(uint32_t*)(g_oh + ro_hi + c) = pack_f16(h2, h3);
        *(uint32_t*)(g_ol + ro_hi + c) = pack_f16(l2, l3);
    }
}

// ---------------- launch ----------------------------------------------------
extern "C" void kernel_launch(void* const* d_in, const int* in_sizes, int n_in,
                              void* d_out, int out_size)
{
    const float* x    = (const float*)d_in[0];
    const float* fcos = (const float*)d_in[2];
    const float* fsin = (const float*)d_in[3];
    const float* wq   = (const float*)d_in[6];
    const float* wk   = (const float*)d_in[7];
    const float* wv   = (const float*)d_in[8];
    const float* wo   = (const float*)d_in[9];
    float* out        = (float*)d_out;

    __half *xh, *xl, *oh, *ol, *wqkv, *wot;
    cudaGetSymbolAddress((void**)&xh, g_xh);
    cudaGetSymbolAddress((void**)&xl, g_xl);
    cudaGetSymbolAddress((void**)&oh, g_oh);
    cudaGetSymbolAddress((void**)&ol, g_ol);
    cudaGetSymbolAddress((void**)&wqkv, g_wqkv);
    cudaGetSymbolAddress((void**)&wot, g_wot);

    cudaFuncSetAttribute(gemm_hmma<0>, cudaFuncAttributeMaxDynamicSharedMemorySize, GEMM_SMEM);
    cudaFuncSetAttribute(gemm_hmma<1>, cudaFuncAttributeMaxDynamicSharedMemorySize, GEMM_SMEM);
    cudaFuncSetAttribute(attn_hmma, cudaFuncAttributeMaxDynamicSharedMemorySize, ATTN_SMEM);

    // launches 1-4: conversions (x split; wq/wk/wv transposed into one array)
    conv_split_kernel<<<(T_ * DIM / 4 + 255) / 256, 256>>>(x, xh, xl, T_ * DIM / 4);
    wconv_kernel<<<dim3(DIM / 32, DIM / 32), dim3(32, 8)>>>(wq, wqkv, DIM);
    wconv_kernel<<<dim3((NKV * HD) / 32, DIM / 32), dim3(32, 8)>>>(wk, wqkv + (size_t)(NH * HD) * DIM, NKV * HD);
    wconv_kernel<<<dim3((NKV * HD) / 32, DIM / 32), dim3(32, 8)>>>(wv, wqkv + (size_t)(NH * HD + NKV * HD) * DIM, NKV * HD);

    // launch 5: fused QKV projection + RoPE + fp16 split
    gemm_hmma<1><<<dim3(NQKV / 256, T_ / 128), 512, GEMM_SMEM>>>(
        xh, xl, wqkv, out, NQKV, fcos, fsin);

    // launch 6: attention
    attn_hmma<<<dim3(S_ / 128, NH, B_), 256, ATTN_SMEM>>>();

    // launches 7-8: wo conversion + output projection
    wconv_kernel<<<dim3(DIM / 32, DIM / 32), dim3(32, 8)>>>(wo, wot, DIM);
    gemm_hmma<0><<<dim3(DIM / 256, T_ / 128), 512, GEMM_SMEM>>>(
        oh, ol, wot, out, DIM, fcos, fsin);
}

// round 11
// speedup vs baseline: 3.2226x; 1.0019x over previous
#include <cuda_runtime.h>
#include <cuda_fp16.h>
#include <cstdint>
#include <math.h>

#define DIM 4096
#define NH  32
#define NKV 8
#define HD  128
#define B_  2
#define S_  2048
#define T_  (B_*S_)          // 4096 tokens
#define NREP 4
#define NQKV 6144            // NH*HD + 2*NKV*HD

// ---------------- scratch (device globals; no cudaMalloc allowed) ----------
__device__ __half g_xh[(size_t)T_ * DIM];
__device__ __half g_xl[(size_t)T_ * DIM];
__device__ __half g_oh[(size_t)T_ * DIM];
__device__ __half g_ol[(size_t)T_ * DIM];
__device__ __half g_qh[(size_t)T_ * NH * HD];
__device__ __half g_ql[(size_t)T_ * NH * HD];
__device__ __half g_kh[(size_t)T_ * NKV * HD];
__device__ __half g_kl[(size_t)T_ * NKV * HD];
__device__ __half g_vh[(size_t)T_ * NKV * HD];
__device__ __half g_wqkv[(size_t)NQKV * DIM];   // [wq | wk | wv] transposed
__device__ __half g_wot[(size_t)DIM * DIM];

// ---------------- low-level helpers (sm_103 base-target safe) --------------
__device__ __forceinline__ uint32_t smem_u32(const void* p) {
    uint32_t a;
    asm("{ .reg .u64 t; cvta.to.shared.u64 t, %1; cvt.u32.u64 %0, t; }"
        : "=r"(a) : "l"(p));
    return a;
}
__device__ __forceinline__ void cp_async16(uint32_t dst, const void* src) {
    asm volatile("cp.async.cg.shared.global [%0], [%1], 16;"
                 :: "r"(dst), "l"(src));
}
#define CP_COMMIT() asm volatile("cp.async.commit_group;" ::: "memory")
#define CP_WAIT(n)  asm volatile("cp.async.wait_group %0;" :: "n"(n) : "memory")

__device__ __forceinline__ void ldsm4(uint32_t& r0, uint32_t& r1,
                                      uint32_t& r2, uint32_t& r3, uint32_t a) {
    asm volatile("ldmatrix.sync.aligned.m8n8.x4.shared.b16 {%0,%1,%2,%3}, [%4];"
                 : "=r"(r0), "=r"(r1), "=r"(r2), "=r"(r3) : "r"(a));
}
__device__ __forceinline__ void ldsm4t(uint32_t& r0, uint32_t& r1,
                                       uint32_t& r2, uint32_t& r3, uint32_t a) {
    asm volatile("ldmatrix.sync.aligned.m8n8.x4.trans.shared.b16 {%0,%1,%2,%3}, [%4];"
                 : "=r"(r0), "=r"(r1), "=r"(r2), "=r"(r3) : "r"(a));
}
__device__ __forceinline__ void mma_f16(float* c, const uint32_t* a,
                                        const uint32_t* b) {
    asm volatile(
        "mma.sync.aligned.m16n8k16.row.col.f32.f16.f16.f32 "
        "{%0,%1,%2,%3}, {%4,%5,%6,%7}, {%8,%9}, {%0,%1,%2,%3};"
        : "+f"(c[0]), "+f"(c[1]), "+f"(c[2]), "+f"(c[3])
        : "r"(a[0]), "r"(a[1]), "r"(a[2]), "r"(a[3]), "r"(b[0]), "r"(b[1]));
}

// ---------------- split-fp16 conversion -------------------------------------
__device__ __forceinline__ void split_f16(float x, __half& h, __half& l)
{
    h = __float2half_rn(x);
    l = __float2half_rn(x - __half2float(h));
}
__device__ __forceinline__ uint32_t pack_f16(__half lo, __half hi)
{
    __half2 v;
    v.x = lo; v.y = hi;
    return *(uint32_t*)&v;
}

__global__ void conv_split_kernel(const float* __restrict__ X,
                                  __half* __restrict__ H,
                                  __half* __restrict__ L, int n4)
{
    int i = blockIdx.x * blockDim.x + threadIdx.x;
    if (i >= n4) return;
    float4 v = *(const float4*)(X + (size_t)i * 4);
    __half h[4], l[4];
    split_f16(v.x, h[0], l[0]);
    split_f16(v.y, h[1], l[1]);
    split_f16(v.z, h[2], l[2]);
    split_f16(v.w, h[3], l[3]);
    *(uint2*)(H + (size_t)i * 4) = *(uint2*)h;
    *(uint2*)(L + (size_t)i * 4) = *(uint2*)l;
}

// transpose + convert: W[K=DIM, N] -> H[N, DIM] fp16 (single weight)
__global__ void wconv_kernel(const float* __restrict__ W,
                             __half* __restrict__ H, int N)
{
    __shared__ float t[32][33];
    const int n0 = blockIdx.x * 32;
    const int k0 = blockIdx.y * 32;
    const int tx = threadIdx.x;
    const int ty = threadIdx.y;
    #pragma unroll
    for (int i = 0; i < 4; i++)
        t[ty + 8 * i][tx] = W[(size_t)(k0 + ty + 8 * i) * N + n0 + tx];
    __syncthreads();
    #pragma unroll
    for (int i = 0; i < 4; i++) {
        float v = t[tx][ty + 8 * i];
        H[(size_t)(n0 + ty + 8 * i) * DIM + k0 + tx] = __float2half_rn(v);
    }
}

// merged transpose+convert of wq|wk|wv into g_wqkv (one launch)
__global__ void wconv_qkv_kernel(const float* __restrict__ wq,
                                 const float* __restrict__ wk,
                                 const float* __restrict__ wv)
{
    __shared__ float t[32][33];
    const int c0 = blockIdx.x * 32;   // combined column tile (0..6143)
    const int k0 = blockIdx.y * 32;
    const int tx = threadIdx.x;
    const int ty = threadIdx.y;

    const float* W;
    int nloc, Nsrc;
    if (c0 < NH * HD)                { W = wq; nloc = c0;                 Nsrc = NH * HD;  }
    else if (c0 < NH * HD + NKV*HD)  { W = wk; nloc = c0 - NH * HD;       Nsrc = NKV * HD; }
    else                             { W = wv; nloc = c0 - NH*HD - NKV*HD; Nsrc = NKV * HD; }

    #pragma unroll
    for (int i = 0; i < 4; i++)
        t[ty + 8 * i][tx] = W[(size_t)(k0 + ty + 8 * i) * Nsrc + nloc + tx];
    __syncthreads();
    #pragma unroll
    for (int i = 0; i < 4; i++) {
        float v = t[tx][ty + 8 * i];
        g_wqkv[(size_t)(c0 + ty + 8 * i) * DIM + k0 + tx] = __float2half_rn(v);
    }
}

// ---------------- HMMA 2-pass split-fp16 GEMM (128x256 tile) ----------------
#define GK       DIM
#define GCHUNKS  (GK / 32)
#define A_H_OFF  0
#define A_L_OFF  8192
#define B_OFF    16384
#define STAGEB   32768              // Ah(8K) + Al(8K) + B(16K)
#define NSTAGE   4
#define GEMM_SMEM (NSTAGE * STAGEB) // 128 KB

__device__ __forceinline__ uint32_t chunk_offA(int row, int kg) {
    return (uint32_t)(kg * 128 + ((row + 2 * kg) & 127)) * 16u;
}
__device__ __forceinline__ uint32_t chunk_offB(int row, int kg) {
    return (uint32_t)(kg * 256 + ((row + 2 * kg) & 255)) * 16u;
}

template<int MODE>
__global__ __launch_bounds__(512, 1) void gemm_hmma(
    const __half* __restrict__ Ah, const __half* __restrict__ Al,
    const __half* __restrict__ B,
    float* __restrict__ C, int N,
    const float* __restrict__ fcos, const float* __restrict__ fsin)
{
    extern __shared__ char smg[];
    const uint32_t sbase = smem_u32(smg);

    const int tid = threadIdx.x;
    const int wid = tid >> 5;
    const int lid = tid & 31;
    const int wm  = wid >> 2;      // 0..3 (32 rows each)
    const int wn  = wid & 3;       // 0..3 (64 cols each)
    const int m0  = blockIdx.y * 128;
    const int n0  = blockIdx.x * 256;

    const int lkg = tid & 3;
    const int lr  = tid >> 2;      // 0..127

    auto load_stage = [&](int stage, int kc) {
        const uint32_t sb = sbase + stage * STAGEB;
        const size_t koff = (size_t)kc * 32 + lkg * 8;
        const uint32_t coA = chunk_offA(lr, lkg);
        const size_t ga = (size_t)(m0 + lr) * GK + koff;
        cp_async16(sb + A_H_OFF + coA, Ah + ga);
        cp_async16(sb + A_L_OFF + coA, Al + ga);
        #pragma unroll
        for (int i = 0; i < 2; i++) {
            const int r = lr + i * 128;
            const uint32_t coB = chunk_offB(r, lkg);
            const size_t gb = (size_t)(n0 + r) * GK + koff;
            cp_async16(sb + B_OFF + coB, B + gb);
        }
    };

    float acc[2][8][4];
    #pragma unroll
    for (int i = 0; i < 2; i++)
        #pragma unroll
        for (int j = 0; j < 8; j++)
            #pragma unroll
            for (int k = 0; k < 4; k++) acc[i][j][k] = 0.f;

    const int sel  = lid >> 3;
    const int lsub = lid & 7;
    const int a_mo = lsub + ((sel & 1) << 3);
    const int a_kg = sel >> 1;
    const int b_no = lsub + ((sel >> 1) << 3);
    const int b_kg = sel & 1;

    load_stage(0, 0); CP_COMMIT();
    load_stage(1, 1); CP_COMMIT();
    load_stage(2, 2); CP_COMMIT();

    for (int kc = 0; kc < GCHUNKS; kc++) {
        const int s = kc & (NSTAGE - 1);
        CP_WAIT(2);
        __syncthreads();

        if (kc + 3 < GCHUNKS) load_stage((kc + 3) & (NSTAGE - 1), kc + 3);
        CP_COMMIT();

        const uint32_t sb = sbase + s * STAGEB;

        #pragma unroll
        for (int ks = 0; ks < 2; ks++) {
            const int kgA = ks * 2 + a_kg;
            const int kgB = ks * 2 + b_kg;

            uint32_t afh[2][4], afl[2][4];
            #pragma unroll
            for (int mt = 0; mt < 2; mt++) {
                const int m = wm * 32 + mt * 16 + a_mo;
                const uint32_t co = chunk_offA(m, kgA);
                ldsm4(afh[mt][0], afh[mt][1], afh[mt][2], afh[mt][3],
                      sb + A_H_OFF + co);
                ldsm4(afl[mt][0], afl[mt][1], afl[mt][2], afl[mt][3],
                      sb + A_L_OFF + co);
            }
            uint32_t bf[4][4];
            #pragma unroll
            for (int nt2 = 0; nt2 < 4; nt2++) {
                const int n = wn * 64 + nt2 * 16 + b_no;
                const uint32_t co = chunk_offB(n, kgB);
                ldsm4(bf[nt2][0], bf[nt2][1], bf[nt2][2], bf[nt2][3],
                      sb + B_OFF + co);
            }
            #pragma unroll
            for (int mt = 0; mt < 2; mt++)
                #pragma unroll
                for (int nt = 0; nt < 8; nt++) {
                    uint32_t b2[2] = { bf[nt >> 1][(nt & 1) << 1],
                                       bf[nt >> 1][((nt & 1) << 1) + 1] };
                    mma_f16(acc[mt][nt], afh[mt], b2);
                    mma_f16(acc[mt][nt], afl[mt], b2);
                }
        }
    }

    const int crow = lid >> 2;
    const int ccol = (lid & 3) * 2;

    if (MODE == 0) {
        #pragma unroll
        for (int mt = 0; mt < 2; mt++) {
            const int r0 = m0 + wm * 32 + mt * 16 + crow;
            #pragma unroll
            for (int nt = 0; nt < 8; nt++) {
                const int c0 = n0 + wn * 64 + nt * 8 + ccol;
                *(float2*)(C + (size_t)r0 * N + c0) =
                    make_float2(acc[mt][nt][0], acc[mt][nt][1]);
                *(float2*)(C + (size_t)(r0 + 8) * N + c0) =
                    make_float2(acc[mt][nt][2], acc[mt][nt][3]);
            }
        }
    } else {
        // fused RoPE + split-fp16 QKV epilogue; route by CTA column block
        const int seg = (n0 < NH * HD) ? 0 : (n0 < NH * HD + NKV * HD ? 1 : 2);
        __half* Hd;
        __half* Ld = nullptr;
        int colbase, rstride;
        if (seg == 0)      { Hd = g_qh; Ld = g_ql; colbase = n0;                rstride = NH * HD;  }
        else if (seg == 1) { Hd = g_kh; Ld = g_kl; colbase = n0 - NH * HD;      rstride = NKV * HD; }
        else               { Hd = g_vh;            colbase = n0 - NH * HD - NKV * HD; rstride = NKV * HD; }

        #pragma unroll
        for (int mt = 0; mt < 2; mt++) {
            const int r0 = m0 + wm * 32 + mt * 16 + crow;
            const int r1 = r0 + 8;
            const int s0 = r0 & (S_ - 1);
            const int s1 = r1 & (S_ - 1);
            #pragma unroll
            for (int nt = 0; nt < 8; nt++) {
                const int c = colbase + wn * 64 + nt * 8 + ccol;
                float v00 = acc[mt][nt][0], v01 = acc[mt][nt][1];
                float v10 = acc[mt][nt][2], v11 = acc[mt][nt][3];
                if (seg < 2) {
                    const int d = (c & (HD - 1)) >> 1;
                    const float c0v = fcos[s0 * (HD / 2) + d];
                    const float s0v = fsin[s0 * (HD / 2) + d];
                    const float c1v = fcos[s1 * (HD / 2) + d];
                    const float s1v = fsin[s1 * (HD / 2) + d];
                    float t00 = v00 * c0v - v01 * s0v;
                    float t01 = v00 * s0v + v01 * c0v;
                    float t10 = v10 * c1v - v11 * s1v;
                    float t11 = v10 * s1v + v11 * c1v;
                    v00 = t00; v01 = t01; v10 = t10; v11 = t11;
                }
                const size_t o0 = (size_t)r0 * rstride + c;
                const size_t o1 = (size_t)r1 * rstride + c;
                __half h0, l0, h1, l1;
                split_f16(v00, h0, l0);
                split_f16(v01, h1, l1);
                *(uint32_t*)(Hd + o0) = pack_f16(h0, h1);
                if (seg < 2) *(uint32_t*)(Ld + o0) = pack_f16(l0, l1);
                split_f16(v10, h0, l0);
                split_f16(v11, h1, l1);
                *(uint32_t*)(Hd + o1) = pack_f16(h0, h1);
                if (seg < 2) *(uint32_t*)(Ld + o1) = pack_f16(l0, l1);
            }
        }
    }
}

// ---------------- HMMA split-fp16 flash attention ---------------------------
// CTA: 128 q rows x one (b, head). S = QK^T 3-pass; O += PV 1-pass (P,V fp16).
// Q fragments cached in registers across the whole kv loop.
#define SQH_OFF 0
#define SQL_OFF 32768
#define STG_OFF 65536
#define STG_SZ  49152              // Kh + Kl + Vh
#define KH_OFF  0
#define KL_OFF  16384
#define VH_OFF  32768
#define ATTN_SMEM (STG_OFF + 2 * STG_SZ)   // 160 KB

__device__ __forceinline__ uint32_t offq(int r, int c) {
    return (uint32_t)(c * 128 + ((r + 2 * c) & 127)) * 16u;
}
__device__ __forceinline__ uint32_t offkv(int r, int c) {
    return (uint32_t)(c * 64 + ((r + 2 * c) & 63)) * 16u;
}

__global__ __launch_bounds__(256, 1) void attn_hmma()
{
    extern __shared__ char sma[];
    const uint32_t sb = smem_u32(sma);

    const int tid = threadIdx.x;
    const int wid = tid >> 5;
    const int lid = tid & 31;
    const int bx  = gridDim.x - 1 - blockIdx.x;   // LPT: longest CTAs first
    const int h   = blockIdx.y;
    const int bz  = blockIdx.z;
    const int g   = h >> 2;
    const int qm0 = bx * 128;
    const int tb  = bz * S_;
    const int ntiles = 2 * (bx + 1);

    const int sel  = lid >> 3;
    const int lsub = lid & 7;
    const int a_r  = wid * 16 + lsub + ((sel & 1) << 3);
    const int a_co = sel >> 1;
    const int b_r  = lsub + ((sel >> 1) << 3);
    const int b_co = sel & 1;
    const int v_r  = lsub + ((sel & 1) << 3);
    const int v_co = sel >> 1;

    const int lc = tid & 15;
    const int lr = tid >> 4;

    // Q (once): 128 rows x 16 chunks x {h,l}
    {
        #pragma unroll
        for (int i = 0; i < 8; i++) {
            const int r = lr + 16 * i;
            const size_t go = ((size_t)(tb + qm0 + r) * NH + h) * HD + lc * 8;
            const uint32_t o = offq(r, lc);
            cp_async16(sb + SQH_OFF + o, g_qh + go);
            cp_async16(sb + SQL_OFF + o, g_ql + go);
        }
    }
    auto load_kv = [&](int stage, int t) {
        const uint32_t st = sb + STG_OFF + stage * STG_SZ;
        const int j0 = t * 64;
        #pragma unroll
        for (int i = 0; i < 4; i++) {
            const int r = lr + 16 * i;
            const size_t go = ((size_t)(tb + j0 + r) * NKV + g) * HD + lc * 8;
            const uint32_t o = offkv(r, lc);
            cp_async16(st + KH_OFF + o, g_kh + go);
            cp_async16(st + KL_OFF + o, g_kl + go);
            cp_async16(st + VH_OFF + o, g_vh + go);
        }
    };

    load_kv(0, 0); CP_COMMIT();                // group 1: Q + tile0
    load_kv(1, 1); CP_COMMIT();                // group 2: tile1 (ntiles >= 2 always)

    // wait for Q + tile0, then cache Q fragments in registers
    CP_WAIT(1);
    __syncthreads();
    uint32_t qfh[8][4], qfl[8][4];
    #pragma unroll
    for (int kt = 0; kt < 8; kt++) {
        const uint32_t qo = offq(a_r, 2 * kt + a_co);
        ldsm4(qfh[kt][0], qfh[kt][1], qfh[kt][2], qfh[kt][3], sb + SQH_OFF + qo);
        ldsm4(qfl[kt][0], qfl[kt][1], qfl[kt][2], qfl[kt][3], sb + SQL_OFF + qo);
    }

    float o[16][4];
    #pragma unroll
    for (int i = 0; i < 16; i++)
        #pragma unroll
        for (int j = 0; j < 4; j++) o[i][j] = 0.f;
    float m_lo = -1e30f, m_hi = -1e30f;
    float l_lo = 0.f, l_hi = 0.f;
    const float scale = 0.08838834764831843f;
    const int row_lo = qm0 + wid * 16 + (lid >> 2);
    const int col_l  = (lid & 3) * 2;

    for (int t = 0; t < ntiles; t++) {
        if (t > 0) {
            if (t + 1 < ntiles) { CP_WAIT(1); } else { CP_WAIT(0); }
            __syncthreads();
        }

        const uint32_t stb = sb + STG_OFF + (t & 1) * STG_SZ;
        const bool masked = (t >= 2 * bx);
        const int j0 = t * 64;

        // ---- S = Q K^T (3-pass fp16) ----
        float sacc[8][4];
        #pragma unroll
        for (int i = 0; i < 8; i++)
            #pragma unroll
            for (int j = 0; j < 4; j++) sacc[i][j] = 0.f;

        #pragma unroll
        for (int kt = 0; kt < 8; kt++) {
            uint32_t kh[4][4], kl[4][4];
            #pragma unroll
            for (int np = 0; np < 4; np++) {
                const uint32_t ko = offkv(np * 16 + b_r, 2 * kt + b_co);
                ldsm4(kh[np][0], kh[np][1], kh[np][2], kh[np][3],
                      stb + KH_OFF + ko);
                ldsm4(kl[np][0], kl[np][1], kl[np][2], kl[np][3],
                      stb + KL_OFF + ko);
            }
            #pragma unroll
            for (int nt = 0; nt < 8; nt++) {
                uint32_t bh[2] = { kh[nt >> 1][(nt & 1) << 1],
                                   kh[nt >> 1][((nt & 1) << 1) + 1] };
                uint32_t bl[2] = { kl[nt >> 1][(nt & 1) << 1],
                                   kl[nt >> 1][((nt & 1) << 1) + 1] };
                mma_f16(sacc[nt], qfh[kt], bh);
                mma_f16(sacc[nt], qfl[kt], bh);
                mma_f16(sacc[nt], qfh[kt], bl);
            }
        }

        // ---- scale + causal mask ----
        if (masked) {
            #pragma unroll
            for (int nt = 0; nt < 8; nt++) {
                const int c0 = j0 + nt * 8 + col_l;
                sacc[nt][0] = (c0     <= row_lo)     ? sacc[nt][0] * scale : -1e30f;
                sacc[nt][1] = (c0 + 1 <= row_lo)     ? sacc[nt][1] * scale : -1e30f;
                sacc[nt][2] = (c0     <= row_lo + 8) ? sacc[nt][2] * scale : -1e30f;
                sacc[nt][3] = (c0 + 1 <= row_lo + 8) ? sacc[nt][3] * scale : -1e30f;
            }
        } else {
            #pragma unroll
            for (int nt = 0; nt < 8; nt++)
                #pragma unroll
                for (int e = 0; e < 4; e++) sacc[nt][e] *= scale;
        }

        // ---- online softmax ----
        float mx_lo = -1e30f, mx_hi = -1e30f;
        #pragma unroll
        for (int nt = 0; nt < 8; nt++) {
            mx_lo = fmaxf(mx_lo, fmaxf(sacc[nt][0], sacc[nt][1]));
            mx_hi = fmaxf(mx_hi, fmaxf(sacc[nt][2], sacc[nt][3]));
        }
        #pragma unroll
        for (int off = 1; off < 4; off <<= 1) {
            mx_lo = fmaxf(mx_lo, __shfl_xor_sync(0xffffffffu, mx_lo, off));
            mx_hi = fmaxf(mx_hi, __shfl_xor_sync(0xffffffffu, mx_hi, off));
        }
        const float mn_lo = fmaxf(m_lo, mx_lo);
        const float mn_hi = fmaxf(m_hi, mx_hi);
        const float al_lo = __expf(m_lo - mn_lo);
        const float al_hi = __expf(m_hi - mn_hi);
        m_lo = mn_lo; m_hi = mn_hi;

        float sum_lo = 0.f, sum_hi = 0.f;
        uint32_t aph[4][4];
        #pragma unroll
        for (int kt2 = 0; kt2 < 4; kt2++) {
            float p[2][4];
            #pragma unroll
            for (int half = 0; half < 2; half++) {
                const int nt = 2 * kt2 + half;
                p[half][0] = __expf(sacc[nt][0] - mn_lo);
                p[half][1] = __expf(sacc[nt][1] - mn_lo);
                p[half][2] = __expf(sacc[nt][2] - mn_hi);
                p[half][3] = __expf(sacc[nt][3] - mn_hi);
                sum_lo += p[half][0] + p[half][1];
                sum_hi += p[half][2] + p[half][3];
            }
            #pragma unroll
            for (int half = 0; half < 2; half++) {
                aph[kt2][0 + 2 * half] = pack_f16(__float2half_rn(p[half][0]),
                                                  __float2half_rn(p[half][1]));
                aph[kt2][1 + 2 * half] = pack_f16(__float2half_rn(p[half][2]),
                                                  __float2half_rn(p[half][3]));
            }
        }
        #pragma unroll
        for (int off = 1; off < 4; off <<= 1) {
            sum_lo += __shfl_xor_sync(0xffffffffu, sum_lo, off);
            sum_hi += __shfl_xor_sync(0xffffffffu, sum_hi, off);
        }
        l_lo = l_lo * al_lo + sum_lo;
        l_hi = l_hi * al_hi + sum_hi;
        #pragma unroll
        for (int dt = 0; dt < 16; dt++) {
            o[dt][0] *= al_lo; o[dt][1] *= al_lo;
            o[dt][2] *= al_hi; o[dt][3] *= al_hi;
        }

        // ---- O += P V (1-pass fp16) ----
        #pragma unroll
        for (int kt2 = 0; kt2 < 4; kt2++) {
            #pragma unroll
            for (int dp = 0; dp < 8; dp++) {
                uint32_t vh[4];
                const uint32_t vo = offkv(kt2 * 16 + v_r, 2 * dp + v_co);
                ldsm4t(vh[0], vh[1], vh[2], vh[3], stb + VH_OFF + vo);
                #pragma unroll
                for (int d2 = 0; d2 < 2; d2++) {
                    const int dt = 2 * dp + d2;
                    uint32_t bh[2] = { vh[d2 * 2], vh[d2 * 2 + 1] };
                    mma_f16(o[dt], aph[kt2], bh);
                }
            }
        }

        __syncthreads();
        if (t + 2 < ntiles) { load_kv(t & 1, t + 2); }
        CP_COMMIT();
    }

    // ---- epilogue: normalize + split-fp16 store ----
    const float inv_lo = 1.f / l_lo;
    const float inv_hi = 1.f / l_hi;
    const size_t ro_lo = ((size_t)(tb + row_lo) * NH + h) * HD;
    const size_t ro_hi = ro_lo + (size_t)8 * NH * HD;
    #pragma unroll
    for (int dt = 0; dt < 16; dt++) {
        const int c = dt * 8 + col_l;
        float f0 = o[dt][0] * inv_lo, f1 = o[dt][1] * inv_lo;
        float f2 = o[dt][2] * inv_hi, f3 = o[dt][3] * inv_hi;
        __half h0, l0, h1, l1, h2, l2, h3, l3;
        split_f16(f0, h0, l0);
        split_f16(f1, h1, l1);
        split_f16(f2, h2, l2);
        split_f16(f3, h3, l3);
        *(uint32_t*)(g_oh + ro_lo + c) = pack_f16(h0, h1);
        *(uint32_t*)(g_ol + ro_lo + c) = pack_f16(l0, l1);
        *(uint32_t*)(g_oh + ro_hi + c) = pack_f16(h2, h3);
        *(uint32_t*)(g_ol + ro_hi + c) = pack_f16(l2, l3);
    }
}

// ---------------- launch ----------------------------------------------------
extern "C" void kernel_launch(void* const* d_in, const int* in_sizes, int n_in,
                              void* d_out, int out_size)
{
    const float* x    = (const float*)d_in[0];
    const float* fcos = (const float*)d_in[2];
    const float* fsin = (const float*)d_in[3];
    const float* wq   = (const float*)d_in[6];
    const float* wk   = (const float*)d_in[7];
    const float* wv   = (const float*)d_in[8];
    const float* wo   = (const float*)d_in[9];
    float* out        = (float*)d_out;

    __half *xh, *xl, *oh, *ol, *wqkv, *wot;
    cudaGetSymbolAddress((void**)&xh, g_xh);
    cudaGetSymbolAddress((void**)&xl, g_xl);
    cudaGetSymbolAddress((void**)&oh, g_oh);
    cudaGetSymbolAddress((void**)&ol, g_ol);
    cudaGetSymbolAddress((void**)&wqkv, g_wqkv);
    cudaGetSymbolAddress((void**)&wot, g_wot);

    cudaFuncSetAttribute(gemm_hmma<0>, cudaFuncAttributeMaxDynamicSharedMemorySize, GEMM_SMEM);
    cudaFuncSetAttribute(gemm_hmma<1>, cudaFuncAttributeMaxDynamicSharedMemorySize, GEMM_SMEM);
    cudaFuncSetAttribute(attn_hmma, cudaFuncAttributeMaxDynamicSharedMemorySize, ATTN_SMEM);

    // launch 1: x split
    conv_split_kernel<<<(T_ * DIM / 4 + 255) / 256, 256>>>(x, xh, xl, T_ * DIM / 4);
    // launch 2: merged wq|wk|wv transpose+convert
    wconv_qkv_kernel<<<dim3(NQKV / 32, DIM / 32), dim3(32, 8)>>>(wq, wk, wv);
    // launch 3: wo transpose+convert
    wconv_kernel<<<dim3(DIM / 32, DIM / 32), dim3(32, 8)>>>(wo, wot, DIM);

    // launch 4 (profiled): fused QKV projection + RoPE + fp16 split
    gemm_hmma<1><<<dim3(NQKV / 256, T_ / 128), 512, GEMM_SMEM>>>(
        xh, xl, wqkv, out, NQKV, fcos, fsin);

    // launch 5: attention
    attn_hmma<<<dim3(S_ / 128, NH, B_), 256, ATTN_SMEM>>>();

    // launch 6: output projection
    gemm_hmma<0><<<dim3(DIM / 256, T_ / 128), 512, GEMM_SMEM>>>(
        oh, ol, wot, out, DIM, fcos, fsin);
}